// round 6
// baseline (speedup 1.0000x reference)
#include <cuda_runtime.h>
#include <cstdint>

// ===================== device scratch (no allocation) =====================
__device__ float g_off[8 * 18 * 128 * 128];   // offset conv output
__device__ float g_whi[8 * 72 * 64];          // main W tf32: [j][kk=tap*8+s][q]
__device__ float g_owhi[8 * 72 * 32];         // offset W tf32: [j][kk][gid*4+nt]

// ===================== helpers =====================
__device__ __forceinline__ uint32_t f2tf32(float f) {
    uint32_t r;
    asm("cvt.rna.tf32.f32 %0, %1;" : "=r"(r) : "f"(f));
    return r;
}
__device__ __forceinline__ void mma8(float* d,
                                     uint32_t a0, uint32_t a1, uint32_t a2, uint32_t a3,
                                     uint32_t b0, uint32_t b1) {
    asm volatile(
        "mma.sync.aligned.m16n8k8.row.col.f32.tf32.tf32.f32 "
        "{%0,%1,%2,%3}, {%4,%5,%6,%7}, {%8,%9}, {%0,%1,%2,%3};"
        : "+f"(d[0]), "+f"(d[1]), "+f"(d[2]), "+f"(d[3])
        : "r"(a0), "r"(a1), "r"(a2), "r"(a3), "r"(b0), "r"(b1));
}

// bilinear sample of a channel PAIR; interior -> float2 smem tile (stride 30)
__device__ __forceinline__ float2 bsample2(const float2* __restrict__ xt_cp,
                                           const float* __restrict__ xg0,
                                           const float* __restrict__ xg1,
                                           int val, float4 wv) {
    if (val >= 0) {
        float2 c0 = xt_cp[val], c1 = xt_cp[val + 1];
        float2 c2 = xt_cp[val + 30], c3 = xt_cp[val + 31];
        float vx = wv.x * c0.x + wv.y * c1.x + wv.z * c2.x + wv.w * c3.x;
        float vy = wv.x * c0.y + wv.y * c1.y + wv.z * c2.y + wv.w * c3.y;
        return make_float2(vx, vy);
    }
    int iy = ((val >> 8) & 0xff) - 2;
    int ix = (val & 0xff) - 2;
    bool m00 = ((unsigned)iy < 128u) & ((unsigned)ix < 128u);
    bool m01 = ((unsigned)iy < 128u) & ((unsigned)(ix + 1) < 128u);
    bool m10 = ((unsigned)(iy + 1) < 128u) & ((unsigned)ix < 128u);
    bool m11 = ((unsigned)(iy + 1) < 128u) & ((unsigned)(ix + 1) < 128u);
    int i00 = iy * 128 + ix;
    float vx = wv.x * (m00 ? xg0[i00] : 0.f) + wv.y * (m01 ? xg0[i00 + 1] : 0.f)
             + wv.z * (m10 ? xg0[i00 + 128] : 0.f) + wv.w * (m11 ? xg0[i00 + 129] : 0.f);
    float vy = wv.x * (m00 ? xg1[i00] : 0.f) + wv.y * (m01 ? xg1[i00 + 1] : 0.f)
             + wv.z * (m10 ? xg1[i00 + 128] : 0.f) + wv.w * (m11 ? xg1[i00 + 129] : 0.f);
    return make_float2(vx, vy);
}

// ===================== prep: weight layouts =====================
// k-slot s within a chunk holds channel 2*(s&3) + (s>>2)  (pairs lanes' slots)
__global__ void wprep_kernel(const float* __restrict__ dw,
                             const float* __restrict__ ow) {
    int i = blockIdx.x * 256 + threadIdx.x;
    if (i < 36864) {           // main W
        int j = i / 4608, r = i - j * 4608;
        int kk = r >> 6, q = r & 63;
        int tap = kk >> 3, s = kk & 7;
        int c = j * 8 + 2 * (s & 3) + (s >> 2);
        int o = (q & 7) * 8 + (q >> 3);
        g_whi[i] = __uint_as_float(f2tf32(dw[o * 576 + c * 9 + tap]));
    }
    if (i < 18432) {           // offset W: [j][kk][gid*4+nt]
        int j = i / 2304, r = i - j * 2304;
        int kk = r >> 5, col = r & 31;
        int tap = kk >> 3, s = kk & 7;
        int c = j * 8 + 2 * (s & 3) + (s >> 2);
        int nt = col & 3, g = col >> 2;
        int o = nt * 8 + g;
        float wv = (nt < 3 && o < 18) ? ow[o * 576 + c * 9 + tap] : 0.f;
        g_owhi[i] = __uint_as_float(f2tf32(wv));
    }
}

// ===================== stage 1: offset conv via mma (tf32) =====================
__global__ __launch_bounds__(256) void offconv_kernel(
    const float* __restrict__ x, const float* __restrict__ ob)
{
    __shared__ float2 xt2[1296];        // 4 cpairs x 18x18 (halo 1)
    __shared__ float wh[2304];          // [kk][32]

    int tid = threadIdx.x, w = tid >> 5, lane = tid & 31;
    int gid = lane >> 2, tig = lane & 3;
    int b = blockIdx.z, ty = blockIdx.y * 16, tx = blockIdx.x * 16;
    const float* xb = x + (size_t)b * 64 * 16384;

    float acc0[3][4], acc1[3][4];
#pragma unroll
    for (int n = 0; n < 3; n++)
#pragma unroll
        for (int i = 0; i < 4; i++) { acc0[n][i] = 0.f; acc1[n][i] = 0.f; }

    for (int j = 0; j < 8; j++) {
        __syncthreads();
        const float* xc = xb + (size_t)j * 8 * 16384;
        for (int t = tid; t < 1296; t += 256) {
            int cp = t / 324, pos = t - cp * 324;
            int rr = pos / 18, cl = pos - rr * 18;
            int gy = ty - 1 + rr, gx = tx - 1 + cl;
            float2 v = make_float2(0.f, 0.f);
            if ((unsigned)gy < 128u && (unsigned)gx < 128u) {
                const float* s = xc + 2 * cp * 16384 + gy * 128 + gx;
                v.x = __uint_as_float(f2tf32(s[0]));
                v.y = __uint_as_float(f2tf32(s[16384]));
            }
            xt2[t] = v;
        }
        for (int t = tid; t < 2304; t += 256) wh[t] = g_owhi[j * 2304 + t];
        __syncthreads();

#pragma unroll
        for (int kt = 0; kt < 9; kt++) {
            int dty = kt / 3, dtx = kt - dty * 3;
            const float2* ap = xt2 + tig * 324 + (2 * w + dty) * 18 + gid + dtx;
            float2 f0 = ap[0], f1 = ap[8], f2v = ap[18], f3 = ap[26];
            float4 bA = *(const float4*)(wh + (kt * 8 + tig) * 32 + gid * 4);
            float4 bB = *(const float4*)(wh + (kt * 8 + tig + 4) * 32 + gid * 4);
            uint32_t a0 = __float_as_uint(f0.x), a1 = __float_as_uint(f1.x);
            uint32_t a2 = __float_as_uint(f0.y), a3 = __float_as_uint(f1.y);
            uint32_t g0 = __float_as_uint(f2v.x), g1 = __float_as_uint(f3.x);
            uint32_t g2 = __float_as_uint(f2v.y), g3 = __float_as_uint(f3.y);
            mma8(acc0[0], a0, a1, a2, a3, __float_as_uint(bA.x), __float_as_uint(bB.x));
            mma8(acc0[1], a0, a1, a2, a3, __float_as_uint(bA.y), __float_as_uint(bB.y));
            mma8(acc0[2], a0, a1, a2, a3, __float_as_uint(bA.z), __float_as_uint(bB.z));
            mma8(acc1[0], g0, g1, g2, g3, __float_as_uint(bA.x), __float_as_uint(bB.x));
            mma8(acc1[1], g0, g1, g2, g3, __float_as_uint(bA.y), __float_as_uint(bB.y));
            mma8(acc1[2], g0, g1, g2, g3, __float_as_uint(bA.z), __float_as_uint(bB.z));
        }
    }

    int yA = ty + 2 * w, xA = tx + gid, xB = xA + 8;
    size_t bb = (size_t)b * 18 * 16384;
#pragma unroll
    for (int nt = 0; nt < 3; nt++) {
        int o0 = nt * 8 + 2 * tig;
        if (o0 < 18) {
            float bs = ob[o0];
            float* pl = g_off + bb + (size_t)o0 * 16384;
            pl[yA * 128 + xA]       = acc0[nt][0] + bs;
            pl[yA * 128 + xB]       = acc0[nt][2] + bs;
            pl[(yA + 1) * 128 + xA] = acc1[nt][0] + bs;
            pl[(yA + 1) * 128 + xB] = acc1[nt][2] + bs;
        }
        if (o0 + 1 < 18) {
            float bs = ob[o0 + 1];
            float* pl = g_off + bb + (size_t)(o0 + 1) * 16384;
            pl[yA * 128 + xA]       = acc0[nt][1] + bs;
            pl[yA * 128 + xB]       = acc0[nt][3] + bs;
            pl[(yA + 1) * 128 + xA] = acc1[nt][1] + bs;
            pl[(yA + 1) * 128 + xB] = acc1[nt][3] + bs;
        }
    }
}

// ===================== SMEM layout main (float index) =====================
// sw4  : 2304 x float4  (premultiplied bilinear weights)   [0, 9216)
// spk  : 2304 x int                                        [9216, 11520)
// xt2  : 4 cpairs x 29x30 float2 = 6960 floats             [11520, 18480)
// whs  : 72 x 68                                           [18480, 23376)
#define SM_W4  0
#define SM_SPK 9216
#define SM_XT  11520
#define SM_WHI 18480
#define SMEM_MAIN_BYTES (23376 * 4)

// ===================== stage 2: gather + tf32 mma (A hi only) ==============
// Block 16x16 pixels (M=256), 512 threads = 16 warps; warp = one m16 tile
// (one image row of 16 px). N=64. K tap-major, 8ch/chunk.
__global__ __launch_bounds__(512) void deform_main_kernel(
    const float* __restrict__ x, const float* __restrict__ db,
    float* __restrict__ out)
{
    extern __shared__ __align__(16) float smf[];
    float4* sw4  = (float4*)(smf + SM_W4);      // 2304
    int*    spk  = (int*)(smf + SM_SPK);        // 2304
    float2* xt2  = (float2*)(smf + SM_XT);      // 4 cpairs x 870
    float*  whs  = smf + SM_WHI;                // [72][68]

    int tid = threadIdx.x, w = tid >> 5, lane = tid & 31;
    int gid = lane >> 2, tig = lane & 3;
    int b = blockIdx.z, ty = blockIdx.y * 16, tx = blockIdx.x * 16;
    const float* xb = x + (size_t)b * 64 * 16384;

    // ---- prologue: per (tap,pixel) metadata ----
    for (int e = tid; e < 2304; e += 512) {
        int k = e >> 8, p = e & 255;
        int yy = ty + (p >> 4), xx = tx + (p & 15);
        float dy = g_off[((size_t)b * 18 + 2 * k) * 16384 + yy * 128 + xx];
        float dx = g_off[((size_t)b * 18 + 2 * k + 1) * 16384 + yy * 128 + xx];
        float py = (float)(yy + k / 3 - 1) + dy;
        float px = (float)(xx + k % 3 - 1) + dx;
        float fy = floorf(py), fx = floorf(px);
        float wy = py - fy, wx = px - fx;
        float oy = 1.f - wy, ox = 1.f - wx;
        sw4[e] = make_float4(oy * ox, oy * wx, wy * ox, wy * wx);
        // clamp to [-2,128]: clamped region has all-invalid corners -> exact 0
        int iy = (int)fminf(fmaxf(fy, -2.f), 128.f);
        int ix = (int)fminf(fmaxf(fx, -2.f), 128.f);
        int ly = iy - (ty - 6), lx = ix - (tx - 6);
        int val;
        if ((unsigned)ly < 28u && (unsigned)lx < 29u)
            val = ly * 30 + lx;
        else
            val = (int)(0x80000000u | ((unsigned)(iy + 2) << 8) | (unsigned)(ix + 2));
        spk[e] = val;
    }

    float acc[8][4];
#pragma unroll
    for (int n = 0; n < 8; n++)
#pragma unroll
        for (int i = 0; i < 4; i++) acc[n][i] = 0.f;

    const int p0 = w * 16 + gid;

    for (int j = 0; j < 8; j++) {
        __syncthreads();
        const float* xc = xb + (size_t)j * 8 * 16384;
        // x tile: 4 channel pairs x 29x30 (halo 6), float2
        for (int t = tid; t < 3480; t += 512) {
            int cp = t / 870, pos = t - cp * 870;
            int rr = pos / 30, cl = pos - rr * 30;
            int gy = ty - 6 + rr, gx = tx - 6 + cl;
            float2 v = make_float2(0.f, 0.f);
            if ((unsigned)gy < 128u && (unsigned)gx < 128u) {
                const float* s = xc + 2 * cp * 16384 + gy * 128 + gx;
                v.x = s[0];
                v.y = s[16384];
            }
            xt2[t] = v;
        }
        {
            const float4* src = (const float4*)(g_whi + j * 4608);
            for (int t = tid; t < 1152; t += 512) {
                int kk = t >> 4, q4 = t & 15;
                *(float4*)(whs + kk * 68 + q4 * 4) = src[t];
            }
        }
        __syncthreads();

        const float2* xtc = xt2 + tig * 870;
        const float* xg0 = xc + (size_t)(2 * tig) * 16384;
        const float* xg1 = xg0 + 16384;

#pragma unroll
        for (int kt = 0; kt < 9; kt++) {
            int ib = kt * 256 + p0;
            float4 W0 = sw4[ib];     int q0 = spk[ib];
            float4 W1 = sw4[ib + 8]; int q1 = spk[ib + 8];

            float2 s0 = bsample2(xtc, xg0, xg1, q0, W0);
            float2 s1 = bsample2(xtc, xg0, xg1, q1, W1);

            uint32_t a0 = f2tf32(s0.x), a1 = f2tf32(s1.x);
            uint32_t a2 = f2tf32(s0.y), a3 = f2tf32(s1.y);

            int rb = (kt * 8 + tig) * 68 + gid * 8;
            float4 b0a = *(const float4*)(whs + rb);
            float4 b0b = *(const float4*)(whs + rb + 4);
            float4 b1a = *(const float4*)(whs + rb + 272);
            float4 b1b = *(const float4*)(whs + rb + 276);

            mma8(acc[0], a0, a1, a2, a3, __float_as_uint(b0a.x), __float_as_uint(b1a.x));
            mma8(acc[1], a0, a1, a2, a3, __float_as_uint(b0a.y), __float_as_uint(b1a.y));
            mma8(acc[2], a0, a1, a2, a3, __float_as_uint(b0a.z), __float_as_uint(b1a.z));
            mma8(acc[3], a0, a1, a2, a3, __float_as_uint(b0a.w), __float_as_uint(b1a.w));
            mma8(acc[4], a0, a1, a2, a3, __float_as_uint(b0b.x), __float_as_uint(b1b.x));
            mma8(acc[5], a0, a1, a2, a3, __float_as_uint(b0b.y), __float_as_uint(b1b.y));
            mma8(acc[6], a0, a1, a2, a3, __float_as_uint(b0b.z), __float_as_uint(b1b.z));
            mma8(acc[7], a0, a1, a2, a3, __float_as_uint(b0b.w), __float_as_uint(b1b.w));
        }
    }

    // ---- epilogue: bias + relu ----
    int y = ty + w, xA = tx + gid, xB = xA + 8;
    float* obp = out + (size_t)b * 64 * 16384;
#pragma unroll
    for (int nt = 0; nt < 8; nt++) {
        int o0 = nt * 8 + 2 * tig;
        float bs0 = db[o0], bs1 = db[o0 + 1];
        float* pl0 = obp + (size_t)o0 * 16384;
        float* pl1 = pl0 + 16384;
        pl0[y * 128 + xA] = fmaxf(acc[nt][0] + bs0, 0.f);
        pl1[y * 128 + xA] = fmaxf(acc[nt][1] + bs1, 0.f);
        pl0[y * 128 + xB] = fmaxf(acc[nt][2] + bs0, 0.f);
        pl1[y * 128 + xB] = fmaxf(acc[nt][3] + bs1, 0.f);
    }
}

// ===================== launch =====================
extern "C" void kernel_launch(void* const* d_in, const int* in_sizes, int n_in,
                              void* d_out, int out_size) {
    const float* x        = (const float*)d_in[0];  // (8,64,128,128)
    const float* offset_w = (const float*)d_in[1];  // (18,64,3,3)
    const float* offset_b = (const float*)d_in[2];  // (18,)
    const float* deform_w = (const float*)d_in[3];  // (64,64,3,3)
    const float* deform_b = (const float*)d_in[4];  // (64,)
    float* out = (float*)d_out;                     // (8,64,128,128)

    cudaFuncSetAttribute(deform_main_kernel,
                         cudaFuncAttributeMaxDynamicSharedMemorySize,
                         SMEM_MAIN_BYTES);

    wprep_kernel<<<144, 256>>>(deform_w, offset_w);
    offconv_kernel<<<dim3(8, 8, 8), 256>>>(x, offset_b);
    deform_main_kernel<<<dim3(8, 8, 8), 512, SMEM_MAIN_BYTES>>>(x, deform_b, out);
}

// round 7
// speedup vs baseline: 1.0860x; 1.0860x over previous
#include <cuda_runtime.h>
#include <cstdint>

// ===================== device scratch (no allocation) =====================
__device__ float g_off[8 * 18 * 128 * 128];   // offset conv output
__device__ float g_whi[8 * 72 * 64];          // main W tf32: [j][kk=tap*8+s][q]
__device__ float g_owhi[8 * 72 * 32];         // offset W tf32: [j][kk][gid*4+nt]

// ===================== helpers =====================
__device__ __forceinline__ uint32_t f2tf32(float f) {
    uint32_t r;
    asm("cvt.rna.tf32.f32 %0, %1;" : "=r"(r) : "f"(f));
    return r;
}
__device__ __forceinline__ void mma8(float* d,
                                     uint32_t a0, uint32_t a1, uint32_t a2, uint32_t a3,
                                     uint32_t b0, uint32_t b1) {
    asm volatile(
        "mma.sync.aligned.m16n8k8.row.col.f32.tf32.tf32.f32 "
        "{%0,%1,%2,%3}, {%4,%5,%6,%7}, {%8,%9}, {%0,%1,%2,%3};"
        : "+f"(d[0]), "+f"(d[1]), "+f"(d[2]), "+f"(d[3])
        : "r"(a0), "r"(a1), "r"(a2), "r"(a3), "r"(b0), "r"(b1));
}

// bilinear sample of a channel PAIR; interior -> float2 smem tile (stride 30)
__device__ __forceinline__ float2 bsample2(const float2* __restrict__ xt_cp,
                                           const float* __restrict__ xg0,
                                           const float* __restrict__ xg1,
                                           int val, float4 wv) {
    if (val >= 0) {
        float2 c0 = xt_cp[val], c1 = xt_cp[val + 1];
        float2 c2 = xt_cp[val + 30], c3 = xt_cp[val + 31];
        float vx = wv.x * c0.x + wv.y * c1.x + wv.z * c2.x + wv.w * c3.x;
        float vy = wv.x * c0.y + wv.y * c1.y + wv.z * c2.y + wv.w * c3.y;
        return make_float2(vx, vy);
    }
    int iy = ((val >> 8) & 0xff) - 2;
    int ix = (val & 0xff) - 2;
    bool m00 = ((unsigned)iy < 128u) & ((unsigned)ix < 128u);
    bool m01 = ((unsigned)iy < 128u) & ((unsigned)(ix + 1) < 128u);
    bool m10 = ((unsigned)(iy + 1) < 128u) & ((unsigned)ix < 128u);
    bool m11 = ((unsigned)(iy + 1) < 128u) & ((unsigned)(ix + 1) < 128u);
    int i00 = iy * 128 + ix;
    float vx = wv.x * (m00 ? xg0[i00] : 0.f) + wv.y * (m01 ? xg0[i00 + 1] : 0.f)
             + wv.z * (m10 ? xg0[i00 + 128] : 0.f) + wv.w * (m11 ? xg0[i00 + 129] : 0.f);
    float vy = wv.x * (m00 ? xg1[i00] : 0.f) + wv.y * (m01 ? xg1[i00 + 1] : 0.f)
             + wv.z * (m10 ? xg1[i00 + 128] : 0.f) + wv.w * (m11 ? xg1[i00 + 129] : 0.f);
    return make_float2(vx, vy);
}

// ===================== prep: weight layouts =====================
// k-slot s within a chunk holds channel 2*(s&3) + (s>>2)  (pairs lanes' slots)
__global__ void wprep_kernel(const float* __restrict__ dw,
                             const float* __restrict__ ow) {
    int i = blockIdx.x * 256 + threadIdx.x;
    if (i < 36864) {           // main W
        int j = i / 4608, r = i - j * 4608;
        int kk = r >> 6, q = r & 63;
        int tap = kk >> 3, s = kk & 7;
        int c = j * 8 + 2 * (s & 3) + (s >> 2);
        int o = (q & 7) * 8 + (q >> 3);
        g_whi[i] = __uint_as_float(f2tf32(dw[o * 576 + c * 9 + tap]));
    }
    if (i < 18432) {           // offset W: [j][kk][gid*4+nt]
        int j = i / 2304, r = i - j * 2304;
        int kk = r >> 5, col = r & 31;
        int tap = kk >> 3, s = kk & 7;
        int c = j * 8 + 2 * (s & 3) + (s >> 2);
        int nt = col & 3, g = col >> 2;
        int o = nt * 8 + g;
        float wv = (nt < 3 && o < 18) ? ow[o * 576 + c * 9 + tap] : 0.f;
        g_owhi[i] = __uint_as_float(f2tf32(wv));
    }
}

// ===================== stage 1: offset conv via mma (tf32) =====================
__global__ __launch_bounds__(256, 2) void offconv_kernel(
    const float* __restrict__ x, const float* __restrict__ ob)
{
    __shared__ float2 xt2[1296];        // 4 cpairs x 18x18 (halo 1)
    __shared__ float wh[2304];          // [kk][32]

    int tid = threadIdx.x, w = tid >> 5, lane = tid & 31;
    int gid = lane >> 2, tig = lane & 3;
    int b = blockIdx.z, ty = blockIdx.y * 16, tx = blockIdx.x * 16;
    const float* xb = x + (size_t)b * 64 * 16384;

    float acc0[3][4], acc1[3][4];
#pragma unroll
    for (int n = 0; n < 3; n++)
#pragma unroll
        for (int i = 0; i < 4; i++) { acc0[n][i] = 0.f; acc1[n][i] = 0.f; }

    for (int j = 0; j < 8; j++) {
        __syncthreads();
        const float* xc = xb + (size_t)j * 8 * 16384;
        for (int t = tid; t < 1296; t += 256) {
            int cp = t / 324, pos = t - cp * 324;
            int rr = pos / 18, cl = pos - rr * 18;
            int gy = ty - 1 + rr, gx = tx - 1 + cl;
            float2 v = make_float2(0.f, 0.f);
            if ((unsigned)gy < 128u && (unsigned)gx < 128u) {
                const float* s = xc + 2 * cp * 16384 + gy * 128 + gx;
                v.x = __uint_as_float(f2tf32(s[0]));
                v.y = __uint_as_float(f2tf32(s[16384]));
            }
            xt2[t] = v;
        }
        for (int t = tid; t < 2304; t += 256) wh[t] = g_owhi[j * 2304 + t];
        __syncthreads();

#pragma unroll
        for (int kt = 0; kt < 9; kt++) {
            int dty = kt / 3, dtx = kt - dty * 3;
            const float2* ap = xt2 + tig * 324 + (2 * w + dty) * 18 + gid + dtx;
            float2 f0 = ap[0], f1 = ap[8], f2v = ap[18], f3 = ap[26];
            float4 bA = *(const float4*)(wh + (kt * 8 + tig) * 32 + gid * 4);
            float4 bB = *(const float4*)(wh + (kt * 8 + tig + 4) * 32 + gid * 4);
            uint32_t a0 = __float_as_uint(f0.x), a1 = __float_as_uint(f1.x);
            uint32_t a2 = __float_as_uint(f0.y), a3 = __float_as_uint(f1.y);
            uint32_t g0 = __float_as_uint(f2v.x), g1 = __float_as_uint(f3.x);
            uint32_t g2 = __float_as_uint(f2v.y), g3 = __float_as_uint(f3.y);
            mma8(acc0[0], a0, a1, a2, a3, __float_as_uint(bA.x), __float_as_uint(bB.x));
            mma8(acc0[1], a0, a1, a2, a3, __float_as_uint(bA.y), __float_as_uint(bB.y));
            mma8(acc0[2], a0, a1, a2, a3, __float_as_uint(bA.z), __float_as_uint(bB.z));
            mma8(acc1[0], g0, g1, g2, g3, __float_as_uint(bA.x), __float_as_uint(bB.x));
            mma8(acc1[1], g0, g1, g2, g3, __float_as_uint(bA.y), __float_as_uint(bB.y));
            mma8(acc1[2], g0, g1, g2, g3, __float_as_uint(bA.z), __float_as_uint(bB.z));
        }
    }

    int yA = ty + 2 * w, xA = tx + gid, xB = xA + 8;
    size_t bb = (size_t)b * 18 * 16384;
#pragma unroll
    for (int nt = 0; nt < 3; nt++) {
        int o0 = nt * 8 + 2 * tig;
        if (o0 < 18) {
            float bs = ob[o0];
            float* pl = g_off + bb + (size_t)o0 * 16384;
            pl[yA * 128 + xA]       = acc0[nt][0] + bs;
            pl[yA * 128 + xB]       = acc0[nt][2] + bs;
            pl[(yA + 1) * 128 + xA] = acc1[nt][0] + bs;
            pl[(yA + 1) * 128 + xB] = acc1[nt][2] + bs;
        }
        if (o0 + 1 < 18) {
            float bs = ob[o0 + 1];
            float* pl = g_off + bb + (size_t)(o0 + 1) * 16384;
            pl[yA * 128 + xA]       = acc0[nt][1] + bs;
            pl[yA * 128 + xB]       = acc0[nt][3] + bs;
            pl[(yA + 1) * 128 + xA] = acc1[nt][1] + bs;
            pl[(yA + 1) * 128 + xB] = acc1[nt][3] + bs;
        }
    }
}

// ===================== SMEM layout main (float index) =====================
// sw4  : 2304 x float4  (premultiplied bilinear weights)   [0, 9216)
// spk  : 2304 x int                                        [9216, 11520)
// xt2  : 4 cpairs x 29x30 float2 = 6960 floats             [11520, 18480)
// whs  : 72 x 68                                           [18480, 23376)
#define SM_W4  0
#define SM_SPK 9216
#define SM_XT  11520
#define SM_WHI 18480
#define SMEM_MAIN_BYTES (23376 * 4)

// ===================== stage 2: gather + tf32 mma (A hi only) ==============
// Block 16x16 pixels (M=256), 256 threads = 8 warps; warp = 32 px (2 m16 tiles).
// N=64. K tap-major, 8ch/chunk. Forced 2 blocks/SM residency.
__global__ __launch_bounds__(256, 2) void deform_main_kernel(
    const float* __restrict__ x, const float* __restrict__ db,
    float* __restrict__ out)
{
    extern __shared__ __align__(16) float smf[];
    float4* sw4  = (float4*)(smf + SM_W4);      // 2304
    int*    spk  = (int*)(smf + SM_SPK);        // 2304
    float2* xt2  = (float2*)(smf + SM_XT);      // 4 cpairs x 870
    float*  whs  = smf + SM_WHI;                // [72][68]

    int tid = threadIdx.x, w = tid >> 5, lane = tid & 31;
    int gid = lane >> 2, tig = lane & 3;
    int b = blockIdx.z, ty = blockIdx.y * 16, tx = blockIdx.x * 16;
    const float* xb = x + (size_t)b * 64 * 16384;

    // ---- prologue: per (tap,pixel) metadata, premultiplied bilinear w ----
    for (int e = tid; e < 2304; e += 256) {
        int k = e >> 8, p = e & 255;
        int yy = ty + (p >> 4), xx = tx + (p & 15);
        float dy = g_off[((size_t)b * 18 + 2 * k) * 16384 + yy * 128 + xx];
        float dx = g_off[((size_t)b * 18 + 2 * k + 1) * 16384 + yy * 128 + xx];
        float py = (float)(yy + k / 3 - 1) + dy;
        float px = (float)(xx + k % 3 - 1) + dx;
        float fy = floorf(py), fx = floorf(px);
        float wy = py - fy, wx = px - fx;
        float oy = 1.f - wy, ox = 1.f - wx;
        sw4[e] = make_float4(oy * ox, oy * wx, wy * ox, wy * wx);
        // clamp to [-2,128]: clamped region has all-invalid corners -> exact 0
        int iy = (int)fminf(fmaxf(fy, -2.f), 128.f);
        int ix = (int)fminf(fmaxf(fx, -2.f), 128.f);
        int ly = iy - (ty - 6), lx = ix - (tx - 6);
        int val;
        if ((unsigned)ly < 28u && (unsigned)lx < 29u)
            val = ly * 30 + lx;
        else
            val = (int)(0x80000000u | ((unsigned)(iy + 2) << 8) | (unsigned)(ix + 2));
        spk[e] = val;
    }

    float acc0[8][4], acc1[8][4];
#pragma unroll
    for (int n = 0; n < 8; n++)
#pragma unroll
        for (int i = 0; i < 4; i++) { acc0[n][i] = 0.f; acc1[n][i] = 0.f; }

    const int p0 = w * 32 + gid;

    for (int j = 0; j < 8; j++) {
        __syncthreads();
        const float* xc = xb + (size_t)j * 8 * 16384;
        // x tile: 4 channel pairs x 29x30 (halo 6), float2
        for (int t = tid; t < 3480; t += 256) {
            int cp = t / 870, pos = t - cp * 870;
            int rr = pos / 30, cl = pos - rr * 30;
            int gy = ty - 6 + rr, gx = tx - 6 + cl;
            float2 v = make_float2(0.f, 0.f);
            if ((unsigned)gy < 128u && (unsigned)gx < 128u) {
                const float* s = xc + 2 * cp * 16384 + gy * 128 + gx;
                v.x = s[0];
                v.y = s[16384];
            }
            xt2[t] = v;
        }
        {
            const float4* src = (const float4*)(g_whi + j * 4608);
            for (int t = tid; t < 1152; t += 256) {
                int kk = t >> 4, q4 = t & 15;
                *(float4*)(whs + kk * 68 + q4 * 4) = src[t];
            }
        }
        __syncthreads();

        const float2* xtc = xt2 + tig * 870;
        const float* xg0 = xc + (size_t)(2 * tig) * 16384;
        const float* xg1 = xg0 + 16384;

#pragma unroll
        for (int kt = 0; kt < 9; kt++) {
            int ib = kt * 256 + p0;
            float4 W0 = sw4[ib];      int q0 = spk[ib];
            float4 W1 = sw4[ib + 8];  int q1 = spk[ib + 8];
            float4 W2 = sw4[ib + 16]; int q2 = spk[ib + 16];
            float4 W3 = sw4[ib + 24]; int q3 = spk[ib + 24];

            float2 s0 = bsample2(xtc, xg0, xg1, q0, W0);
            float2 s1 = bsample2(xtc, xg0, xg1, q1, W1);
            float2 s2 = bsample2(xtc, xg0, xg1, q2, W2);
            float2 s3 = bsample2(xtc, xg0, xg1, q3, W3);

            uint32_t a0 = f2tf32(s0.x), a1 = f2tf32(s1.x);
            uint32_t a2 = f2tf32(s0.y), a3 = f2tf32(s1.y);
            uint32_t g0 = f2tf32(s2.x), g1 = f2tf32(s3.x);
            uint32_t g2 = f2tf32(s2.y), g3 = f2tf32(s3.y);

            int rb = (kt * 8 + tig) * 68 + gid * 8;
            float4 b0a = *(const float4*)(whs + rb);
            float4 b0b = *(const float4*)(whs + rb + 4);
            float4 b1a = *(const float4*)(whs + rb + 272);
            float4 b1b = *(const float4*)(whs + rb + 276);
            uint32_t B0[8] = {
                __float_as_uint(b0a.x), __float_as_uint(b0a.y),
                __float_as_uint(b0a.z), __float_as_uint(b0a.w),
                __float_as_uint(b0b.x), __float_as_uint(b0b.y),
                __float_as_uint(b0b.z), __float_as_uint(b0b.w)};
            uint32_t B1[8] = {
                __float_as_uint(b1a.x), __float_as_uint(b1a.y),
                __float_as_uint(b1a.z), __float_as_uint(b1a.w),
                __float_as_uint(b1b.x), __float_as_uint(b1b.y),
                __float_as_uint(b1b.z), __float_as_uint(b1b.w)};

#pragma unroll
            for (int nt = 0; nt < 8; nt++) {
                mma8(acc0[nt], a0, a1, a2, a3, B0[nt], B1[nt]);
                mma8(acc1[nt], g0, g1, g2, g3, B0[nt], B1[nt]);
            }
        }
    }

    // ---- epilogue: bias + relu ----
    int yA = ty + 2 * w, xA = tx + gid, xB = xA + 8;
    float* obp = out + (size_t)b * 64 * 16384;
#pragma unroll
    for (int nt = 0; nt < 8; nt++) {
        int o0 = nt * 8 + 2 * tig;
        float bs0 = db[o0], bs1 = db[o0 + 1];
        float* pl0 = obp + (size_t)o0 * 16384;
        float* pl1 = pl0 + 16384;
        pl0[yA * 128 + xA]       = fmaxf(acc0[nt][0] + bs0, 0.f);
        pl1[yA * 128 + xA]       = fmaxf(acc0[nt][1] + bs1, 0.f);
        pl0[yA * 128 + xB]       = fmaxf(acc0[nt][2] + bs0, 0.f);
        pl1[yA * 128 + xB]       = fmaxf(acc0[nt][3] + bs1, 0.f);
        pl0[(yA + 1) * 128 + xA] = fmaxf(acc1[nt][0] + bs0, 0.f);
        pl1[(yA + 1) * 128 + xA] = fmaxf(acc1[nt][1] + bs1, 0.f);
        pl0[(yA + 1) * 128 + xB] = fmaxf(acc1[nt][2] + bs0, 0.f);
        pl1[(yA + 1) * 128 + xB] = fmaxf(acc1[nt][3] + bs1, 0.f);
    }
}

// ===================== launch =====================
extern "C" void kernel_launch(void* const* d_in, const int* in_sizes, int n_in,
                              void* d_out, int out_size) {
    const float* x        = (const float*)d_in[0];  // (8,64,128,128)
    const float* offset_w = (const float*)d_in[1];  // (18,64,3,3)
    const float* offset_b = (const float*)d_in[2];  // (18,)
    const float* deform_w = (const float*)d_in[3];  // (64,64,3,3)
    const float* deform_b = (const float*)d_in[4];  // (64,)
    float* out = (float*)d_out;                     // (8,64,128,128)

    cudaFuncSetAttribute(deform_main_kernel,
                         cudaFuncAttributeMaxDynamicSharedMemorySize,
                         SMEM_MAIN_BYTES);

    wprep_kernel<<<144, 256>>>(deform_w, offset_w);
    offconv_kernel<<<dim3(8, 8, 8), 256>>>(x, offset_b);
    deform_main_kernel<<<dim3(8, 8, 8), 256, SMEM_MAIN_BYTES>>>(x, deform_b, out);
}

// round 8
// speedup vs baseline: 1.1000x; 1.0128x over previous
#include <cuda_runtime.h>
#include <cuda_fp16.h>
#include <cstdint>

// ===================== device scratch (no allocation) =====================
__device__ float g_off[8 * 18 * 128 * 128];   // offset conv output
__device__ uint2 g_wh16[8 * 5 * 4 * 64];      // main W fp16x2: [j][g][tig][gid][nt]
__device__ float g_owhi[8 * 72 * 32];         // offset W tf32: [j][kk][gid*4+nt]

// ===================== helpers =====================
__device__ __forceinline__ uint32_t f2tf32(float f) {
    uint32_t r;
    asm("cvt.rna.tf32.f32 %0, %1;" : "=r"(r) : "f"(f));
    return r;
}
__device__ __forceinline__ uint32_t packf16(float2 s) {
    uint32_t r;   // lo half = s.x (first PTX source goes to upper half)
    asm("cvt.rn.f16x2.f32 %0, %1, %2;" : "=r"(r) : "f"(s.y), "f"(s.x));
    return r;
}
__device__ __forceinline__ void mma8(float* d,
                                     uint32_t a0, uint32_t a1, uint32_t a2, uint32_t a3,
                                     uint32_t b0, uint32_t b1) {
    asm volatile(
        "mma.sync.aligned.m16n8k8.row.col.f32.tf32.tf32.f32 "
        "{%0,%1,%2,%3}, {%4,%5,%6,%7}, {%8,%9}, {%0,%1,%2,%3};"
        : "+f"(d[0]), "+f"(d[1]), "+f"(d[2]), "+f"(d[3])
        : "r"(a0), "r"(a1), "r"(a2), "r"(a3), "r"(b0), "r"(b1));
}
__device__ __forceinline__ void mma16(float* d,
                                      uint32_t a0, uint32_t a1, uint32_t a2, uint32_t a3,
                                      uint32_t b0, uint32_t b1) {
    asm volatile(
        "mma.sync.aligned.m16n8k16.row.col.f32.f16.f16.f32 "
        "{%0,%1,%2,%3}, {%4,%5,%6,%7}, {%8,%9}, {%0,%1,%2,%3};"
        : "+f"(d[0]), "+f"(d[1]), "+f"(d[2]), "+f"(d[3])
        : "r"(a0), "r"(a1), "r"(a2), "r"(a3), "r"(b0), "r"(b1));
}

// bilinear sample of a channel PAIR; interior -> float2 smem tile (stride 30)
__device__ __forceinline__ float2 bsample2(const float2* __restrict__ xt_cp,
                                           const float* __restrict__ xg0,
                                           const float* __restrict__ xg1,
                                           int val, float4 wv) {
    if (val >= 0) {
        float2 c0 = xt_cp[val], c1 = xt_cp[val + 1];
        float2 c2 = xt_cp[val + 30], c3 = xt_cp[val + 31];
        float vx = wv.x * c0.x + wv.y * c1.x + wv.z * c2.x + wv.w * c3.x;
        float vy = wv.x * c0.y + wv.y * c1.y + wv.z * c2.y + wv.w * c3.y;
        return make_float2(vx, vy);
    }
    int iy = ((val >> 8) & 0xff) - 2;
    int ix = (val & 0xff) - 2;
    bool m00 = ((unsigned)iy < 128u) & ((unsigned)ix < 128u);
    bool m01 = ((unsigned)iy < 128u) & ((unsigned)(ix + 1) < 128u);
    bool m10 = ((unsigned)(iy + 1) < 128u) & ((unsigned)ix < 128u);
    bool m11 = ((unsigned)(iy + 1) < 128u) & ((unsigned)(ix + 1) < 128u);
    int i00 = iy * 128 + ix;
    float vx = wv.x * (m00 ? xg0[i00] : 0.f) + wv.y * (m01 ? xg0[i00 + 1] : 0.f)
             + wv.z * (m10 ? xg0[i00 + 128] : 0.f) + wv.w * (m11 ? xg0[i00 + 129] : 0.f);
    float vy = wv.x * (m00 ? xg1[i00] : 0.f) + wv.y * (m01 ? xg1[i00 + 1] : 0.f)
             + wv.z * (m10 ? xg1[i00 + 128] : 0.f) + wv.w * (m11 ? xg1[i00 + 129] : 0.f);
    return make_float2(vx, vy);
}

// ===================== prep: weight layouts =====================
__global__ void wprep_kernel(const float* __restrict__ dw,
                             const float* __restrict__ ow) {
    int i = blockIdx.x * 256 + threadIdx.x;
    if (i < 10240) {           // main W -> fp16x2, mma16 B-fragment order
        int j = i / 1280, r = i - j * 1280;
        int g = r >> 8, r2 = r & 255;
        int tg = r2 >> 6, r3 = r2 & 63;
        int gd = r3 >> 3, nt = r3 & 7;
        int o = nt * 8 + gd;
        int c0 = j * 8 + 2 * tg;
        int tap0 = 2 * g, tap1 = 2 * g + 1;
        __half2 h0 = __floats2half2_rn(dw[o * 576 + c0 * 9 + tap0],
                                       dw[o * 576 + (c0 + 1) * 9 + tap0]);
        __half2 h1 = (tap1 < 9)
            ? __floats2half2_rn(dw[o * 576 + c0 * 9 + tap1],
                                dw[o * 576 + (c0 + 1) * 9 + tap1])
            : __floats2half2_rn(0.f, 0.f);
        uint2 v;
        v.x = *(uint32_t*)&h0;
        v.y = *(uint32_t*)&h1;
        g_wh16[i] = v;
    }
    if (i < 18432) {           // offset W tf32: [j][kk][gid*4+nt]
        int j = i / 2304, r = i - j * 2304;
        int kk = r >> 5, col = r & 31;
        int tap = kk >> 3, s = kk & 7;
        int c = j * 8 + 2 * (s & 3) + (s >> 2);
        int nt = col & 3, g = col >> 2;
        int o = nt * 8 + g;
        float wv = (nt < 3 && o < 18) ? ow[o * 576 + c * 9 + tap] : 0.f;
        g_owhi[i] = __uint_as_float(f2tf32(wv));
    }
}

// ===================== stage 1: offset conv via mma (tf32) =====================
__global__ __launch_bounds__(256, 2) void offconv_kernel(
    const float* __restrict__ x, const float* __restrict__ ob)
{
    __shared__ float2 xt2[1296];        // 4 cpairs x 18x18 (halo 1)
    __shared__ float wh[2304];          // [kk][32]

    int tid = threadIdx.x, w = tid >> 5, lane = tid & 31;
    int gid = lane >> 2, tig = lane & 3;
    int b = blockIdx.z, ty = blockIdx.y * 16, tx = blockIdx.x * 16;
    const float* xb = x + (size_t)b * 64 * 16384;

    float acc0[3][4], acc1[3][4];
#pragma unroll
    for (int n = 0; n < 3; n++)
#pragma unroll
        for (int i = 0; i < 4; i++) { acc0[n][i] = 0.f; acc1[n][i] = 0.f; }

    for (int j = 0; j < 8; j++) {
        __syncthreads();
        const float* xc = xb + (size_t)j * 8 * 16384;
        for (int t = tid; t < 1296; t += 256) {
            int cp = t / 324, pos = t - cp * 324;
            int rr = pos / 18, cl = pos - rr * 18;
            int gy = ty - 1 + rr, gx = tx - 1 + cl;
            float2 v = make_float2(0.f, 0.f);
            if ((unsigned)gy < 128u && (unsigned)gx < 128u) {
                const float* s = xc + 2 * cp * 16384 + gy * 128 + gx;
                v.x = __uint_as_float(f2tf32(s[0]));
                v.y = __uint_as_float(f2tf32(s[16384]));
            }
            xt2[t] = v;
        }
        for (int t = tid; t < 2304; t += 256) wh[t] = g_owhi[j * 2304 + t];
        __syncthreads();

#pragma unroll
        for (int kt = 0; kt < 9; kt++) {
            int dty = kt / 3, dtx = kt - dty * 3;
            const float2* ap = xt2 + tig * 324 + (2 * w + dty) * 18 + gid + dtx;
            float2 f0 = ap[0], f1 = ap[8], f2v = ap[18], f3 = ap[26];
            float4 bA = *(const float4*)(wh + (kt * 8 + tig) * 32 + gid * 4);
            float4 bB = *(const float4*)(wh + (kt * 8 + tig + 4) * 32 + gid * 4);
            uint32_t a0 = __float_as_uint(f0.x), a1 = __float_as_uint(f1.x);
            uint32_t a2 = __float_as_uint(f0.y), a3 = __float_as_uint(f1.y);
            uint32_t g0 = __float_as_uint(f2v.x), g1 = __float_as_uint(f3.x);
            uint32_t g2 = __float_as_uint(f2v.y), g3 = __float_as_uint(f3.y);
            mma8(acc0[0], a0, a1, a2, a3, __float_as_uint(bA.x), __float_as_uint(bB.x));
            mma8(acc0[1], a0, a1, a2, a3, __float_as_uint(bA.y), __float_as_uint(bB.y));
            mma8(acc0[2], a0, a1, a2, a3, __float_as_uint(bA.z), __float_as_uint(bB.z));
            mma8(acc1[0], g0, g1, g2, g3, __float_as_uint(bA.x), __float_as_uint(bB.x));
            mma8(acc1[1], g0, g1, g2, g3, __float_as_uint(bA.y), __float_as_uint(bB.y));
            mma8(acc1[2], g0, g1, g2, g3, __float_as_uint(bA.z), __float_as_uint(bB.z));
        }
    }

    int yA = ty + 2 * w, xA = tx + gid, xB = xA + 8;
    size_t bb = (size_t)b * 18 * 16384;
#pragma unroll
    for (int nt = 0; nt < 3; nt++) {
        int o0 = nt * 8 + 2 * tig;
        if (o0 < 18) {
            float bs = ob[o0];
            float* pl = g_off + bb + (size_t)o0 * 16384;
            pl[yA * 128 + xA]       = acc0[nt][0] + bs;
            pl[yA * 128 + xB]       = acc0[nt][2] + bs;
            pl[(yA + 1) * 128 + xA] = acc1[nt][0] + bs;
            pl[(yA + 1) * 128 + xB] = acc1[nt][2] + bs;
        }
        if (o0 + 1 < 18) {
            float bs = ob[o0 + 1];
            float* pl = g_off + bb + (size_t)(o0 + 1) * 16384;
            pl[yA * 128 + xA]       = acc0[nt][1] + bs;
            pl[yA * 128 + xB]       = acc0[nt][3] + bs;
            pl[(yA + 1) * 128 + xA] = acc1[nt][1] + bs;
            pl[(yA + 1) * 128 + xB] = acc1[nt][3] + bs;
        }
    }
}

// ===================== SMEM layout main (float index) =====================
// sw4  : 2304 x float4                                     [0, 9216)
// spk  : 2304 x int                                        [9216, 11520)
// xt2  : 4 cpairs x 29x30 float2 = 6960 floats             [11520, 18480)
// wh16 : 1280 x uint2 = 2560 floats                        [18480, 21040)
#define SM_W4  0
#define SM_SPK 9216
#define SM_XT  11520
#define SM_WH  18480
#define SMEM_MAIN_BYTES (21040 * 4)

// ===================== stage 2: gather + fp16 mma16 (f32 accum) ============
// Block 16x16 pixels (M=256), 256 threads = 8 warps; warp = 32 px (2 m16 tiles).
// N=64. K = 8ch/chunk x 10 taps (tap 9 = pad, W=0, A reused).
__global__ __launch_bounds__(256, 2) void deform_main_kernel(
    const float* __restrict__ x, const float* __restrict__ db,
    float* __restrict__ out)
{
    extern __shared__ __align__(16) float smf[];
    float4* sw4  = (float4*)(smf + SM_W4);      // 2304
    int*    spk  = (int*)(smf + SM_SPK);        // 2304
    float2* xt2  = (float2*)(smf + SM_XT);      // 4 cpairs x 870
    uint2*  wh16 = (uint2*)(smf + SM_WH);       // [g][tig][gid][nt]

    int tid = threadIdx.x, w = tid >> 5, lane = tid & 31;
    int gid = lane >> 2, tig = lane & 3;
    int b = blockIdx.z, ty = blockIdx.y * 16, tx = blockIdx.x * 16;
    const float* xb = x + (size_t)b * 64 * 16384;

    // ---- prologue: per (tap,pixel) metadata, premultiplied bilinear w ----
    for (int e = tid; e < 2304; e += 256) {
        int k = e >> 8, p = e & 255;
        int yy = ty + (p >> 4), xx = tx + (p & 15);
        float dy = g_off[((size_t)b * 18 + 2 * k) * 16384 + yy * 128 + xx];
        float dx = g_off[((size_t)b * 18 + 2 * k + 1) * 16384 + yy * 128 + xx];
        float py = (float)(yy + k / 3 - 1) + dy;
        float px = (float)(xx + k % 3 - 1) + dx;
        float fy = floorf(py), fx = floorf(px);
        float wy = py - fy, wx = px - fx;
        float oy = 1.f - wy, ox = 1.f - wx;
        sw4[e] = make_float4(oy * ox, oy * wx, wy * ox, wy * wx);
        // clamp to [-2,128]: clamped region has all-invalid corners -> exact 0
        int iy = (int)fminf(fmaxf(fy, -2.f), 128.f);
        int ix = (int)fminf(fmaxf(fx, -2.f), 128.f);
        int ly = iy - (ty - 6), lx = ix - (tx - 6);
        int val;
        if ((unsigned)ly < 28u && (unsigned)lx < 29u)
            val = ly * 30 + lx;
        else
            val = (int)(0x80000000u | ((unsigned)(iy + 2) << 8) | (unsigned)(ix + 2));
        spk[e] = val;
    }

    float acc0[8][4], acc1[8][4];
#pragma unroll
    for (int n = 0; n < 8; n++)
#pragma unroll
        for (int i = 0; i < 4; i++) { acc0[n][i] = 0.f; acc1[n][i] = 0.f; }

    const int p0 = w * 32 + gid;

    for (int j = 0; j < 8; j++) {
        __syncthreads();
        const float* xc = xb + (size_t)j * 8 * 16384;
        // x tile: 4 channel pairs x 29x30 (halo 6), float2
        for (int t = tid; t < 3480; t += 256) {
            int cp = t / 870, pos = t - cp * 870;
            int rr = pos / 30, cl = pos - rr * 30;
            int gy = ty - 6 + rr, gx = tx - 6 + cl;
            float2 v = make_float2(0.f, 0.f);
            if ((unsigned)gy < 128u && (unsigned)gx < 128u) {
                const float* s = xc + 2 * cp * 16384 + gy * 128 + gx;
                v.x = s[0];
                v.y = s[16384];
            }
            xt2[t] = v;
        }
        {
            const uint4* src = (const uint4*)(g_wh16 + j * 1280);
            uint4* dst = (uint4*)wh16;
            for (int t = tid; t < 640; t += 256) dst[t] = src[t];
        }
        __syncthreads();

        const float2* xtc = xt2 + tig * 870;
        const float* xg0 = xc + (size_t)(2 * tig) * 16384;
        const float* xg1 = xg0 + 16384;

#pragma unroll
        for (int g = 0; g < 5; g++) {
            int ib0 = (2 * g) * 256 + p0;
            float2 s00 = bsample2(xtc, xg0, xg1, spk[ib0],      sw4[ib0]);
            float2 s01 = bsample2(xtc, xg0, xg1, spk[ib0 + 8],  sw4[ib0 + 8]);
            float2 s02 = bsample2(xtc, xg0, xg1, spk[ib0 + 16], sw4[ib0 + 16]);
            float2 s03 = bsample2(xtc, xg0, xg1, spk[ib0 + 24], sw4[ib0 + 24]);
            uint32_t a0  = packf16(s00), a1  = packf16(s01);
            uint32_t a0b = packf16(s02), a1b = packf16(s03);
            uint32_t a2, a3, a2b, a3b;
            if (g < 4) {
                int ib1 = ib0 + 256;
                float2 t0 = bsample2(xtc, xg0, xg1, spk[ib1],      sw4[ib1]);
                float2 t1 = bsample2(xtc, xg0, xg1, spk[ib1 + 8],  sw4[ib1 + 8]);
                float2 t2 = bsample2(xtc, xg0, xg1, spk[ib1 + 16], sw4[ib1 + 16]);
                float2 t3 = bsample2(xtc, xg0, xg1, spk[ib1 + 24], sw4[ib1 + 24]);
                a2 = packf16(t0);  a3 = packf16(t1);
                a2b = packf16(t2); a3b = packf16(t3);
            } else {               // pad tap: W=0, any finite A contributes 0
                a2 = a0; a3 = a1; a2b = a0b; a3b = a1b;
            }

            const uint4* Bp = (const uint4*)(wh16 + ((g * 4 + tig) * 8 + gid) * 8);
            uint4 q0 = Bp[0], q1 = Bp[1], q2 = Bp[2], q3 = Bp[3];

            mma16(acc0[0], a0, a1, a2, a3, q0.x, q0.y);
            mma16(acc1[0], a0b, a1b, a2b, a3b, q0.x, q0.y);
            mma16(acc0[1], a0, a1, a2, a3, q0.z, q0.w);
            mma16(acc1[1], a0b, a1b, a2b, a3b, q0.z, q0.w);
            mma16(acc0[2], a0, a1, a2, a3, q1.x, q1.y);
            mma16(acc1[2], a0b, a1b, a2b, a3b, q1.x, q1.y);
            mma16(acc0[3], a0, a1, a2, a3, q1.z, q1.w);
            mma16(acc1[3], a0b, a1b, a2b, a3b, q1.z, q1.w);
            mma16(acc0[4], a0, a1, a2, a3, q2.x, q2.y);
            mma16(acc1[4], a0b, a1b, a2b, a3b, q2.x, q2.y);
            mma16(acc0[5], a0, a1, a2, a3, q2.z, q2.w);
            mma16(acc1[5], a0b, a1b, a2b, a3b, q2.z, q2.w);
            mma16(acc0[6], a0, a1, a2, a3, q3.x, q3.y);
            mma16(acc1[6], a0b, a1b, a2b, a3b, q3.x, q3.y);
            mma16(acc0[7], a0, a1, a2, a3, q3.z, q3.w);
            mma16(acc1[7], a0b, a1b, a2b, a3b, q3.z, q3.w);
        }
    }

    // ---- epilogue: bias + relu ----
    int yA = ty + 2 * w, xA = tx + gid, xB = xA + 8;
    float* obp = out + (size_t)b * 64 * 16384;
#pragma unroll
    for (int nt = 0; nt < 8; nt++) {
        int o0 = nt * 8 + 2 * tig;
        float bs0 = db[o0], bs1 = db[o0 + 1];
        float* pl0 = obp + (size_t)o0 * 16384;
        float* pl1 = pl0 + 16384;
        pl0[yA * 128 + xA]       = fmaxf(acc0[nt][0] + bs0, 0.f);
        pl1[yA * 128 + xA]       = fmaxf(acc0[nt][1] + bs1, 0.f);
        pl0[yA * 128 + xB]       = fmaxf(acc0[nt][2] + bs0, 0.f);
        pl1[yA * 128 + xB]       = fmaxf(acc0[nt][3] + bs1, 0.f);
        pl0[(yA + 1) * 128 + xA] = fmaxf(acc1[nt][0] + bs0, 0.f);
        pl1[(yA + 1) * 128 + xA] = fmaxf(acc1[nt][1] + bs1, 0.f);
        pl0[(yA + 1) * 128 + xB] = fmaxf(acc1[nt][2] + bs0, 0.f);
        pl1[(yA + 1) * 128 + xB] = fmaxf(acc1[nt][3] + bs1, 0.f);
    }
}

// ===================== launch =====================
extern "C" void kernel_launch(void* const* d_in, const int* in_sizes, int n_in,
                              void* d_out, int out_size) {
    const float* x        = (const float*)d_in[0];  // (8,64,128,128)
    const float* offset_w = (const float*)d_in[1];  // (18,64,3,3)
    const float* offset_b = (const float*)d_in[2];  // (18,)
    const float* deform_w = (const float*)d_in[3];  // (64,64,3,3)
    const float* deform_b = (const float*)d_in[4];  // (64,)
    float* out = (float*)d_out;                     // (8,64,128,128)

    cudaFuncSetAttribute(deform_main_kernel,
                         cudaFuncAttributeMaxDynamicSharedMemorySize,
                         SMEM_MAIN_BYTES);

    wprep_kernel<<<144, 256>>>(deform_w, offset_w);
    offconv_kernel<<<dim3(8, 8, 8), 256>>>(x, offset_b);
    deform_main_kernel<<<dim3(8, 8, 8), 256, SMEM_MAIN_BYTES>>>(x, deform_b, out);
}

// round 9
// speedup vs baseline: 1.2660x; 1.1509x over previous
#include <cuda_runtime.h>
#include <cuda_fp16.h>
#include <cstdint>

// ===================== device scratch (no allocation) =====================
__device__ float g_off[8 * 18 * 128 * 128];   // offset conv output
__device__ uint2 g_wh16[8 * 5 * 4 * 64];      // main W fp16x2: [j][g][tig][gid][nt]
__device__ float g_owhi[8 * 72 * 32];         // offset W tf32: [j][kk][gid*4+nt]

// ===================== helpers =====================
__device__ __forceinline__ uint32_t f2tf32(float f) {
    uint32_t r;
    asm("cvt.rna.tf32.f32 %0, %1;" : "=r"(r) : "f"(f));
    return r;
}
__device__ __forceinline__ uint32_t packf16(float2 s) {
    uint32_t r;   // lo half = s.x
    asm("cvt.rn.f16x2.f32 %0, %1, %2;" : "=r"(r) : "f"(s.y), "f"(s.x));
    return r;
}
__device__ __forceinline__ uint32_t hmul2(uint32_t a, uint32_t b) {
    uint32_t d;
    asm("mul.rn.f16x2 %0, %1, %2;" : "=r"(d) : "r"(a), "r"(b));
    return d;
}
__device__ __forceinline__ uint32_t hfma2(uint32_t a, uint32_t b, uint32_t c) {
    uint32_t d;
    asm("fma.rn.f16x2 %0, %1, %2, %3;" : "=r"(d) : "r"(a), "r"(b), "r"(c));
    return d;
}
__device__ __forceinline__ float h2lof(uint32_t h) {
    __half2 v = *(__half2*)&h;
    return __low2float(v);
}
__device__ __forceinline__ void mma8(float* d,
                                     uint32_t a0, uint32_t a1, uint32_t a2, uint32_t a3,
                                     uint32_t b0, uint32_t b1) {
    asm volatile(
        "mma.sync.aligned.m16n8k8.row.col.f32.tf32.tf32.f32 "
        "{%0,%1,%2,%3}, {%4,%5,%6,%7}, {%8,%9}, {%0,%1,%2,%3};"
        : "+f"(d[0]), "+f"(d[1]), "+f"(d[2]), "+f"(d[3])
        : "r"(a0), "r"(a1), "r"(a2), "r"(a3), "r"(b0), "r"(b1));
}
__device__ __forceinline__ void mma16(float* d,
                                      uint32_t a0, uint32_t a1, uint32_t a2, uint32_t a3,
                                      uint32_t b0, uint32_t b1) {
    asm volatile(
        "mma.sync.aligned.m16n8k16.row.col.f32.f16.f16.f32 "
        "{%0,%1,%2,%3}, {%4,%5,%6,%7}, {%8,%9}, {%0,%1,%2,%3};"
        : "+f"(d[0]), "+f"(d[1]), "+f"(d[2]), "+f"(d[3])
        : "r"(a0), "r"(a1), "r"(a2), "r"(a3), "r"(b0), "r"(b1));
}

// bilinear sample of a channel PAIR in half2; interior -> packed half2 tile
// (stride 30). Returns packed half2 (ch0 lo, ch1 hi) = ready mma A register.
__device__ __forceinline__ uint32_t bs2h(const uint32_t* __restrict__ xth_cp,
                                         const float* __restrict__ xg0,
                                         const float* __restrict__ xg1,
                                         int val, uint4 w) {
    if (val >= 0) {
        uint32_t c0 = xth_cp[val], c1 = xth_cp[val + 1];
        uint32_t c2 = xth_cp[val + 30], c3 = xth_cp[val + 31];
        uint32_t t = hmul2(c0, w.x);
        t = hfma2(c1, w.y, t);
        t = hfma2(c2, w.z, t);
        t = hfma2(c3, w.w, t);
        return t;
    }
    // rare fallback: fp32 masked global bilinear
    float w00 = h2lof(w.x), w01 = h2lof(w.y), w10 = h2lof(w.z), w11 = h2lof(w.w);
    int iy = ((val >> 8) & 0xff) - 2;
    int ix = (val & 0xff) - 2;
    bool m00 = ((unsigned)iy < 128u) & ((unsigned)ix < 128u);
    bool m01 = ((unsigned)iy < 128u) & ((unsigned)(ix + 1) < 128u);
    bool m10 = ((unsigned)(iy + 1) < 128u) & ((unsigned)ix < 128u);
    bool m11 = ((unsigned)(iy + 1) < 128u) & ((unsigned)(ix + 1) < 128u);
    int i00 = iy * 128 + ix;
    float vx = w00 * (m00 ? xg0[i00] : 0.f) + w01 * (m01 ? xg0[i00 + 1] : 0.f)
             + w10 * (m10 ? xg0[i00 + 128] : 0.f) + w11 * (m11 ? xg0[i00 + 129] : 0.f);
    float vy = w00 * (m00 ? xg1[i00] : 0.f) + w01 * (m01 ? xg1[i00 + 1] : 0.f)
             + w10 * (m10 ? xg1[i00 + 128] : 0.f) + w11 * (m11 ? xg1[i00 + 129] : 0.f);
    return packf16(make_float2(vx, vy));
}

// ===================== prep: weight layouts =====================
__global__ void wprep_kernel(const float* __restrict__ dw,
                             const float* __restrict__ ow) {
    int i = blockIdx.x * 256 + threadIdx.x;
    if (i < 10240) {           // main W -> fp16x2, mma16 B-fragment order
        int j = i / 1280, r = i - j * 1280;
        int g = r >> 8, r2 = r & 255;
        int tg = r2 >> 6, r3 = r2 & 63;
        int gd = r3 >> 3, nt = r3 & 7;
        int o = nt * 8 + gd;
        int c0 = j * 8 + 2 * tg;
        int tap0 = 2 * g, tap1 = 2 * g + 1;
        __half2 h0 = __floats2half2_rn(dw[o * 576 + c0 * 9 + tap0],
                                       dw[o * 576 + (c0 + 1) * 9 + tap0]);
        __half2 h1 = (tap1 < 9)
            ? __floats2half2_rn(dw[o * 576 + c0 * 9 + tap1],
                                dw[o * 576 + (c0 + 1) * 9 + tap1])
            : __floats2half2_rn(0.f, 0.f);
        uint2 v;
        v.x = *(uint32_t*)&h0;
        v.y = *(uint32_t*)&h1;
        g_wh16[i] = v;
    }
    if (i < 18432) {           // offset W tf32: [j][kk][gid*4+nt]
        int j = i / 2304, r = i - j * 2304;
        int kk = r >> 5, col = r & 31;
        int tap = kk >> 3, s = kk & 7;
        int c = j * 8 + 2 * (s & 3) + (s >> 2);
        int nt = col & 3, g = col >> 2;
        int o = nt * 8 + g;
        float wv = (nt < 3 && o < 18) ? ow[o * 576 + c * 9 + tap] : 0.f;
        g_owhi[i] = __uint_as_float(f2tf32(wv));
    }
}

// ===================== stage 1: offset conv via mma (tf32) =====================
__global__ __launch_bounds__(256, 2) void offconv_kernel(
    const float* __restrict__ x, const float* __restrict__ ob)
{
    __shared__ float2 xt2[1296];        // 4 cpairs x 18x18 (halo 1)
    __shared__ float wh[2304];          // [kk][32]

    int tid = threadIdx.x, w = tid >> 5, lane = tid & 31;
    int gid = lane >> 2, tig = lane & 3;
    int b = blockIdx.z, ty = blockIdx.y * 16, tx = blockIdx.x * 16;
    const float* xb = x + (size_t)b * 64 * 16384;

    float acc0[3][4], acc1[3][4];
#pragma unroll
    for (int n = 0; n < 3; n++)
#pragma unroll
        for (int i = 0; i < 4; i++) { acc0[n][i] = 0.f; acc1[n][i] = 0.f; }

    for (int j = 0; j < 8; j++) {
        __syncthreads();
        const float* xc = xb + (size_t)j * 8 * 16384;
        for (int t = tid; t < 1296; t += 256) {
            int cp = t / 324, pos = t - cp * 324;
            int rr = pos / 18, cl = pos - rr * 18;
            int gy = ty - 1 + rr, gx = tx - 1 + cl;
            float2 v = make_float2(0.f, 0.f);
            if ((unsigned)gy < 128u && (unsigned)gx < 128u) {
                const float* s = xc + 2 * cp * 16384 + gy * 128 + gx;
                v.x = __uint_as_float(f2tf32(s[0]));
                v.y = __uint_as_float(f2tf32(s[16384]));
            }
            xt2[t] = v;
        }
        for (int t = tid; t < 2304; t += 256) wh[t] = g_owhi[j * 2304 + t];
        __syncthreads();

#pragma unroll
        for (int kt = 0; kt < 9; kt++) {
            int dty = kt / 3, dtx = kt - dty * 3;
            const float2* ap = xt2 + tig * 324 + (2 * w + dty) * 18 + gid + dtx;
            float2 f0 = ap[0], f1 = ap[8], f2v = ap[18], f3 = ap[26];
            float4 bA = *(const float4*)(wh + (kt * 8 + tig) * 32 + gid * 4);
            float4 bB = *(const float4*)(wh + (kt * 8 + tig + 4) * 32 + gid * 4);
            uint32_t a0 = __float_as_uint(f0.x), a1 = __float_as_uint(f1.x);
            uint32_t a2 = __float_as_uint(f0.y), a3 = __float_as_uint(f1.y);
            uint32_t g0 = __float_as_uint(f2v.x), g1 = __float_as_uint(f3.x);
            uint32_t g2 = __float_as_uint(f2v.y), g3 = __float_as_uint(f3.y);
            mma8(acc0[0], a0, a1, a2, a3, __float_as_uint(bA.x), __float_as_uint(bB.x));
            mma8(acc0[1], a0, a1, a2, a3, __float_as_uint(bA.y), __float_as_uint(bB.y));
            mma8(acc0[2], a0, a1, a2, a3, __float_as_uint(bA.z), __float_as_uint(bB.z));
            mma8(acc1[0], g0, g1, g2, g3, __float_as_uint(bA.x), __float_as_uint(bB.x));
            mma8(acc1[1], g0, g1, g2, g3, __float_as_uint(bA.y), __float_as_uint(bB.y));
            mma8(acc1[2], g0, g1, g2, g3, __float_as_uint(bA.z), __float_as_uint(bB.z));
        }
    }

    int yA = ty + 2 * w, xA = tx + gid, xB = xA + 8;
    size_t bb = (size_t)b * 18 * 16384;
#pragma unroll
    for (int nt = 0; nt < 3; nt++) {
        int o0 = nt * 8 + 2 * tig;
        if (o0 < 18) {
            float bs = ob[o0];
            float* pl = g_off + bb + (size_t)o0 * 16384;
            pl[yA * 128 + xA]       = acc0[nt][0] + bs;
            pl[yA * 128 + xB]       = acc0[nt][2] + bs;
            pl[(yA + 1) * 128 + xA] = acc1[nt][0] + bs;
            pl[(yA + 1) * 128 + xB] = acc1[nt][2] + bs;
        }
        if (o0 + 1 < 18) {
            float bs = ob[o0 + 1];
            float* pl = g_off + bb + (size_t)(o0 + 1) * 16384;
            pl[yA * 128 + xA]       = acc0[nt][1] + bs;
            pl[yA * 128 + xB]       = acc0[nt][3] + bs;
            pl[(yA + 1) * 128 + xA] = acc1[nt][1] + bs;
            pl[(yA + 1) * 128 + xB] = acc1[nt][3] + bs;
        }
    }
}

// ===================== SMEM layout main (float index) =====================
// sw4h : 2304 x uint4 (duplicated half2 bilinear weights)  [0, 9216)
// spk  : 2304 x int                                        [9216, 11520)
// xth  : 4 cpairs x 870 packed half2                       [11520, 15000)
// wh16 : 1280 x uint2                                      [15000, 17560)
#define SM_W4  0
#define SM_SPK 9216
#define SM_XT  11520
#define SM_WH  15000
#define SMEM_MAIN_BYTES (17560 * 4)

// ===================== stage 2: half2 gather + fp16 mma16 ==================
// Block 16x16 pixels (M=256), 256 threads = 8 warps; warp = 32 px (2 m16 tiles).
// N=64. K = 8ch/chunk x 10 taps (tap 9 = pad, W=0, A reused).
__global__ __launch_bounds__(256, 2) void deform_main_kernel(
    const float* __restrict__ x, const float* __restrict__ db,
    float* __restrict__ out)
{
    extern __shared__ __align__(16) float smf[];
    uint4*    sw4h = (uint4*)(smf + SM_W4);     // 2304
    int*      spk  = (int*)(smf + SM_SPK);      // 2304
    uint32_t* xth  = (uint32_t*)(smf + SM_XT);  // 4 cpairs x 870
    uint2*    wh16 = (uint2*)(smf + SM_WH);     // [g][tig][gid][nt]

    int tid = threadIdx.x, w = tid >> 5, lane = tid & 31;
    int gid = lane >> 2, tig = lane & 3;
    int b = blockIdx.z, ty = blockIdx.y * 16, tx = blockIdx.x * 16;
    const float* xb = x + (size_t)b * 64 * 16384;

    // ---- prologue: per (tap,pixel) metadata, duplicated-half2 weights ----
    for (int e = tid; e < 2304; e += 256) {
        int k = e >> 8, p = e & 255;
        int yy = ty + (p >> 4), xx = tx + (p & 15);
        float dy = g_off[((size_t)b * 18 + 2 * k) * 16384 + yy * 128 + xx];
        float dx = g_off[((size_t)b * 18 + 2 * k + 1) * 16384 + yy * 128 + xx];
        float py = (float)(yy + k / 3 - 1) + dy;
        float px = (float)(xx + k % 3 - 1) + dx;
        float fy = floorf(py), fx = floorf(px);
        float wy = py - fy, wx = px - fx;
        float oy = 1.f - wy, ox = 1.f - wx;
        uint4 wq;
        wq.x = packf16(make_float2(oy * ox, oy * ox));
        wq.y = packf16(make_float2(oy * wx, oy * wx));
        wq.z = packf16(make_float2(wy * ox, wy * ox));
        wq.w = packf16(make_float2(wy * wx, wy * wx));
        sw4h[e] = wq;
        // clamp to [-2,128]: clamped region has all-invalid corners -> exact 0
        int iy = (int)fminf(fmaxf(fy, -2.f), 128.f);
        int ix = (int)fminf(fmaxf(fx, -2.f), 128.f);
        int ly = iy - (ty - 6), lx = ix - (tx - 6);
        int val;
        if ((unsigned)ly < 28u && (unsigned)lx < 29u)
            val = ly * 30 + lx;
        else
            val = (int)(0x80000000u | ((unsigned)(iy + 2) << 8) | (unsigned)(ix + 2));
        spk[e] = val;
    }

    float acc0[8][4], acc1[8][4];
#pragma unroll
    for (int n = 0; n < 8; n++)
#pragma unroll
        for (int i = 0; i < 4; i++) { acc0[n][i] = 0.f; acc1[n][i] = 0.f; }

    const int p0 = w * 32 + gid;

    for (int j = 0; j < 8; j++) {
        __syncthreads();
        const float* xc = xb + (size_t)j * 8 * 16384;
        // x tile: 4 channel pairs x 29x30 (halo 6), packed half2
        for (int t = tid; t < 3480; t += 256) {
            int cp = t / 870, pos = t - cp * 870;
            int rr = pos / 30, cl = pos - rr * 30;
            int gy = ty - 6 + rr, gx = tx - 6 + cl;
            float2 v = make_float2(0.f, 0.f);
            if ((unsigned)gy < 128u && (unsigned)gx < 128u) {
                const float* s = xc + 2 * cp * 16384 + gy * 128 + gx;
                v.x = s[0];
                v.y = s[16384];
            }
            xth[t] = packf16(v);
        }
        {
            const uint4* src = (const uint4*)(g_wh16 + j * 1280);
            uint4* dst = (uint4*)wh16;
            for (int t = tid; t < 640; t += 256) dst[t] = src[t];
        }
        __syncthreads();

        const uint32_t* xtc = xth + tig * 870;
        const float* xg0 = xc + (size_t)(2 * tig) * 16384;
        const float* xg1 = xg0 + 16384;

#pragma unroll
        for (int g = 0; g < 5; g++) {
            int ib0 = (2 * g) * 256 + p0;
            uint32_t a0  = bs2h(xtc, xg0, xg1, spk[ib0],      sw4h[ib0]);
            uint32_t a1  = bs2h(xtc, xg0, xg1, spk[ib0 + 8],  sw4h[ib0 + 8]);
            uint32_t a0b = bs2h(xtc, xg0, xg1, spk[ib0 + 16], sw4h[ib0 + 16]);
            uint32_t a1b = bs2h(xtc, xg0, xg1, spk[ib0 + 24], sw4h[ib0 + 24]);
            uint32_t a2, a3, a2b, a3b;
            if (g < 4) {
                int ib1 = ib0 + 256;
                a2  = bs2h(xtc, xg0, xg1, spk[ib1],      sw4h[ib1]);
                a3  = bs2h(xtc, xg0, xg1, spk[ib1 + 8],  sw4h[ib1 + 8]);
                a2b = bs2h(xtc, xg0, xg1, spk[ib1 + 16], sw4h[ib1 + 16]);
                a3b = bs2h(xtc, xg0, xg1, spk[ib1 + 24], sw4h[ib1 + 24]);
            } else {               // pad tap: W=0, any finite A contributes 0
                a2 = a0; a3 = a1; a2b = a0b; a3b = a1b;
            }

            const uint4* Bp = (const uint4*)(wh16 + ((g * 4 + tig) * 8 + gid) * 8);
            uint4 q0 = Bp[0], q1 = Bp[1], q2 = Bp[2], q3 = Bp[3];

            mma16(acc0[0], a0, a1, a2, a3, q0.x, q0.y);
            mma16(acc1[0], a0b, a1b, a2b, a3b, q0.x, q0.y);
            mma16(acc0[1], a0, a1, a2, a3, q0.z, q0.w);
            mma16(acc1[1], a0b, a1b, a2b, a3b, q0.z, q0.w);
            mma16(acc0[2], a0, a1, a2, a3, q1.x, q1.y);
            mma16(acc1[2], a0b, a1b, a2b, a3b, q1.x, q1.y);
            mma16(acc0[3], a0, a1, a2, a3, q1.z, q1.w);
            mma16(acc1[3], a0b, a1b, a2b, a3b, q1.z, q1.w);
            mma16(acc0[4], a0, a1, a2, a3, q2.x, q2.y);
            mma16(acc1[4], a0b, a1b, a2b, a3b, q2.x, q2.y);
            mma16(acc0[5], a0, a1, a2, a3, q2.z, q2.w);
            mma16(acc1[5], a0b, a1b, a2b, a3b, q2.z, q2.w);
            mma16(acc0[6], a0, a1, a2, a3, q3.x, q3.y);
            mma16(acc1[6], a0b, a1b, a2b, a3b, q3.x, q3.y);
            mma16(acc0[7], a0, a1, a2, a3, q3.z, q3.w);
            mma16(acc1[7], a0b, a1b, a2b, a3b, q3.z, q3.w);
        }
    }

    // ---- epilogue: bias + relu ----
    int yA = ty + 2 * w, xA = tx + gid, xB = xA + 8;
    float* obp = out + (size_t)b * 64 * 16384;
#pragma unroll
    for (int nt = 0; nt < 8; nt++) {
        int o0 = nt * 8 + 2 * tig;
        float bs0 = db[o0], bs1 = db[o0 + 1];
        float* pl0 = obp + (size_t)o0 * 16384;
        float* pl1 = pl0 + 16384;
        pl0[yA * 128 + xA]       = fmaxf(acc0[nt][0] + bs0, 0.f);
        pl1[yA * 128 + xA]       = fmaxf(acc0[nt][1] + bs1, 0.f);
        pl0[yA * 128 + xB]       = fmaxf(acc0[nt][2] + bs0, 0.f);
        pl1[yA * 128 + xB]       = fmaxf(acc0[nt][3] + bs1, 0.f);
        pl0[(yA + 1) * 128 + xA] = fmaxf(acc1[nt][0] + bs0, 0.f);
        pl1[(yA + 1) * 128 + xA] = fmaxf(acc1[nt][1] + bs1, 0.f);
        pl0[(yA + 1) * 128 + xB] = fmaxf(acc1[nt][2] + bs0, 0.f);
        pl1[(yA + 1) * 128 + xB] = fmaxf(acc1[nt][3] + bs1, 0.f);
    }
}

// ===================== launch =====================
extern "C" void kernel_launch(void* const* d_in, const int* in_sizes, int n_in,
                              void* d_out, int out_size) {
    const float* x        = (const float*)d_in[0];  // (8,64,128,128)
    const float* offset_w = (const float*)d_in[1];  // (18,64,3,3)
    const float* offset_b = (const float*)d_in[2];  // (18,)
    const float* deform_w = (const float*)d_in[3];  // (64,64,3,3)
    const float* deform_b = (const float*)d_in[4];  // (64,)
    float* out = (float*)d_out;                     // (8,64,128,128)

    cudaFuncSetAttribute(deform_main_kernel,
                         cudaFuncAttributeMaxDynamicSharedMemorySize,
                         SMEM_MAIN_BYTES);

    wprep_kernel<<<144, 256>>>(deform_w, offset_w);
    offconv_kernel<<<dim3(8, 8, 8), 256>>>(x, offset_b);
    deform_main_kernel<<<dim3(8, 8, 8), 256, SMEM_MAIN_BYTES>>>(x, deform_b, out);
}

// round 10
// speedup vs baseline: 1.2883x; 1.0176x over previous
#include <cuda_runtime.h>
#include <cuda_fp16.h>
#include <cstdint>

// ===================== device scratch (no allocation) =====================
__device__ float g_off[8 * 18 * 128 * 128];   // offset conv output
__device__ uint2 g_wh16[8 * 5 * 4 * 64];      // main W fp16x2: [j][g][tig][gid][nt]
__device__ float g_owhi[8 * 72 * 32];         // offset W tf32: [j][kk][gid*4+nt]

// ===================== helpers =====================
__device__ __forceinline__ uint32_t f2tf32(float f) {
    uint32_t r;
    asm("cvt.rna.tf32.f32 %0, %1;" : "=r"(r) : "f"(f));
    return r;
}
__device__ __forceinline__ uint32_t packf16(float2 s) {
    uint32_t r;   // lo half = s.x
    asm("cvt.rn.f16x2.f32 %0, %1, %2;" : "=r"(r) : "f"(s.y), "f"(s.x));
    return r;
}
__device__ __forceinline__ uint32_t hsub2(uint32_t a, uint32_t b) {
    uint32_t d;
    asm("sub.rn.f16x2 %0, %1, %2;" : "=r"(d) : "r"(a), "r"(b));
    return d;
}
__device__ __forceinline__ uint32_t hfma2(uint32_t a, uint32_t b, uint32_t c) {
    uint32_t d;
    asm("fma.rn.f16x2 %0, %1, %2, %3;" : "=r"(d) : "r"(a), "r"(b), "r"(c));
    return d;
}
__device__ __forceinline__ uint32_t duplo(uint32_t a) {   // low half -> both
    uint32_t d;
    asm("prmt.b32 %0, %1, %1, 0x1010;" : "=r"(d) : "r"(a));
    return d;
}
__device__ __forceinline__ uint32_t duphi(uint32_t a) {   // high half -> both
    uint32_t d;
    asm("prmt.b32 %0, %1, %1, 0x3232;" : "=r"(d) : "r"(a));
    return d;
}
__device__ __forceinline__ float h2lof(uint32_t h) {
    __half2 v = *(__half2*)&h;
    return __low2float(v);
}
__device__ __forceinline__ void mma8(float* d,
                                     uint32_t a0, uint32_t a1, uint32_t a2, uint32_t a3,
                                     uint32_t b0, uint32_t b1) {
    asm volatile(
        "mma.sync.aligned.m16n8k8.row.col.f32.tf32.tf32.f32 "
        "{%0,%1,%2,%3}, {%4,%5,%6,%7}, {%8,%9}, {%0,%1,%2,%3};"
        : "+f"(d[0]), "+f"(d[1]), "+f"(d[2]), "+f"(d[3])
        : "r"(a0), "r"(a1), "r"(a2), "r"(a3), "r"(b0), "r"(b1));
}
__device__ __forceinline__ void mma16(float* d,
                                      uint32_t a0, uint32_t a1, uint32_t a2, uint32_t a3,
                                      uint32_t b0, uint32_t b1) {
    asm volatile(
        "mma.sync.aligned.m16n8k16.row.col.f32.f16.f16.f32 "
        "{%0,%1,%2,%3}, {%4,%5,%6,%7}, {%8,%9}, {%0,%1,%2,%3};"
        : "+f"(d[0]), "+f"(d[1]), "+f"(d[2]), "+f"(d[3])
        : "r"(a0), "r"(a1), "r"(a2), "r"(a3), "r"(b0), "r"(b1));
}

// bilinear sample of a channel PAIR in half2, interpolation form.
// m.x = packed half2 (wy lo, wx hi); m.y = tile offset or fallback coords.
__device__ __forceinline__ uint32_t bs2h(const uint32_t* __restrict__ xth_cp,
                                         const float* __restrict__ xg0,
                                         const float* __restrict__ xg1,
                                         uint2 m) {
    int val = (int)m.y;
    uint32_t wyd = duplo(m.x), wxd = duphi(m.x);
    if (val >= 0) {
        uint32_t c0 = xth_cp[val], c1 = xth_cp[val + 1];
        uint32_t c2 = xth_cp[val + 30], c3 = xth_cp[val + 31];
        uint32_t rx0 = hfma2(hsub2(c1, c0), wxd, c0);
        uint32_t rx1 = hfma2(hsub2(c3, c2), wxd, c2);
        return hfma2(hsub2(rx1, rx0), wyd, rx0);
    }
    // rare fallback: fp32 masked global bilinear
    float wy = h2lof(wyd), wx = h2lof(wxd);
    float oy = 1.f - wy, ox = 1.f - wx;
    float w00 = oy * ox, w01 = oy * wx, w10 = wy * ox, w11 = wy * wx;
    int iy = ((val >> 8) & 0xff) - 2;
    int ix = (val & 0xff) - 2;
    bool m00 = ((unsigned)iy < 128u) & ((unsigned)ix < 128u);
    bool m01 = ((unsigned)iy < 128u) & ((unsigned)(ix + 1) < 128u);
    bool m10 = ((unsigned)(iy + 1) < 128u) & ((unsigned)ix < 128u);
    bool m11 = ((unsigned)(iy + 1) < 128u) & ((unsigned)(ix + 1) < 128u);
    int i00 = iy * 128 + ix;
    float vx = w00 * (m00 ? xg0[i00] : 0.f) + w01 * (m01 ? xg0[i00 + 1] : 0.f)
             + w10 * (m10 ? xg0[i00 + 128] : 0.f) + w11 * (m11 ? xg0[i00 + 129] : 0.f);
    float vy = w00 * (m00 ? xg1[i00] : 0.f) + w01 * (m01 ? xg1[i00 + 1] : 0.f)
             + w10 * (m10 ? xg1[i00 + 128] : 0.f) + w11 * (m11 ? xg1[i00 + 129] : 0.f);
    return packf16(make_float2(vx, vy));
}

// ===================== prep: weight layouts =====================
__global__ void wprep_kernel(const float* __restrict__ dw,
                             const float* __restrict__ ow) {
    int i = blockIdx.x * 256 + threadIdx.x;
    if (i < 10240) {           // main W -> fp16x2, mma16 B-fragment order
        int j = i / 1280, r = i - j * 1280;
        int g = r >> 8, r2 = r & 255;
        int tg = r2 >> 6, r3 = r2 & 63;
        int gd = r3 >> 3, nt = r3 & 7;
        int o = nt * 8 + gd;
        int c0 = j * 8 + 2 * tg;
        int tap0 = 2 * g, tap1 = 2 * g + 1;
        __half2 h0 = __floats2half2_rn(dw[o * 576 + c0 * 9 + tap0],
                                       dw[o * 576 + (c0 + 1) * 9 + tap0]);
        __half2 h1 = (tap1 < 9)
            ? __floats2half2_rn(dw[o * 576 + c0 * 9 + tap1],
                                dw[o * 576 + (c0 + 1) * 9 + tap1])
            : __floats2half2_rn(0.f, 0.f);
        uint2 v;
        v.x = *(uint32_t*)&h0;
        v.y = *(uint32_t*)&h1;
        g_wh16[i] = v;
    }
    if (i < 18432) {           // offset W tf32: [j][kk][gid*4+nt]
        int j = i / 2304, r = i - j * 2304;
        int kk = r >> 5, col = r & 31;
        int tap = kk >> 3, s = kk & 7;
        int c = j * 8 + 2 * (s & 3) + (s >> 2);
        int nt = col & 3, g = col >> 2;
        int o = nt * 8 + g;
        float wv = (nt < 3 && o < 18) ? ow[o * 576 + c * 9 + tap] : 0.f;
        g_owhi[i] = __uint_as_float(f2tf32(wv));
    }
}

// ===================== stage 1: offset conv via mma (tf32) =====================
__global__ __launch_bounds__(256, 2) void offconv_kernel(
    const float* __restrict__ x, const float* __restrict__ ob)
{
    __shared__ float2 xt2[1296];        // 4 cpairs x 18x18 (halo 1)
    __shared__ float wh[2304];          // [kk][32]

    int tid = threadIdx.x, w = tid >> 5, lane = tid & 31;
    int gid = lane >> 2, tig = lane & 3;
    int b = blockIdx.z, ty = blockIdx.y * 16, tx = blockIdx.x * 16;
    const float* xb = x + (size_t)b * 64 * 16384;

    float acc0[3][4], acc1[3][4];
#pragma unroll
    for (int n = 0; n < 3; n++)
#pragma unroll
        for (int i = 0; i < 4; i++) { acc0[n][i] = 0.f; acc1[n][i] = 0.f; }

    for (int j = 0; j < 8; j++) {
        __syncthreads();
        const float* xc = xb + (size_t)j * 8 * 16384;
        for (int t = tid; t < 1296; t += 256) {
            int cp = t / 324, pos = t - cp * 324;
            int rr = pos / 18, cl = pos - rr * 18;
            int gy = ty - 1 + rr, gx = tx - 1 + cl;
            float2 v = make_float2(0.f, 0.f);
            if ((unsigned)gy < 128u && (unsigned)gx < 128u) {
                const float* s = xc + 2 * cp * 16384 + gy * 128 + gx;
                v.x = __uint_as_float(f2tf32(s[0]));
                v.y = __uint_as_float(f2tf32(s[16384]));
            }
            xt2[t] = v;
        }
        for (int t = tid; t < 2304; t += 256) wh[t] = g_owhi[j * 2304 + t];
        __syncthreads();

#pragma unroll
        for (int kt = 0; kt < 9; kt++) {
            int dty = kt / 3, dtx = kt - dty * 3;
            const float2* ap = xt2 + tig * 324 + (2 * w + dty) * 18 + gid + dtx;
            float2 f0 = ap[0], f1 = ap[8], f2v = ap[18], f3 = ap[26];
            float4 bA = *(const float4*)(wh + (kt * 8 + tig) * 32 + gid * 4);
            float4 bB = *(const float4*)(wh + (kt * 8 + tig + 4) * 32 + gid * 4);
            uint32_t a0 = __float_as_uint(f0.x), a1 = __float_as_uint(f1.x);
            uint32_t a2 = __float_as_uint(f0.y), a3 = __float_as_uint(f1.y);
            uint32_t g0 = __float_as_uint(f2v.x), g1 = __float_as_uint(f3.x);
            uint32_t g2 = __float_as_uint(f2v.y), g3 = __float_as_uint(f3.y);
            mma8(acc0[0], a0, a1, a2, a3, __float_as_uint(bA.x), __float_as_uint(bB.x));
            mma8(acc0[1], a0, a1, a2, a3, __float_as_uint(bA.y), __float_as_uint(bB.y));
            mma8(acc0[2], a0, a1, a2, a3, __float_as_uint(bA.z), __float_as_uint(bB.z));
            mma8(acc1[0], g0, g1, g2, g3, __float_as_uint(bA.x), __float_as_uint(bB.x));
            mma8(acc1[1], g0, g1, g2, g3, __float_as_uint(bA.y), __float_as_uint(bB.y));
            mma8(acc1[2], g0, g1, g2, g3, __float_as_uint(bA.z), __float_as_uint(bB.z));
        }
    }

    int yA = ty + 2 * w, xA = tx + gid, xB = xA + 8;
    size_t bb = (size_t)b * 18 * 16384;
#pragma unroll
    for (int nt = 0; nt < 3; nt++) {
        int o0 = nt * 8 + 2 * tig;
        if (o0 < 18) {
            float bs = ob[o0];
            float* pl = g_off + bb + (size_t)o0 * 16384;
            pl[yA * 128 + xA]       = acc0[nt][0] + bs;
            pl[yA * 128 + xB]       = acc0[nt][2] + bs;
            pl[(yA + 1) * 128 + xA] = acc1[nt][0] + bs;
            pl[(yA + 1) * 128 + xB] = acc1[nt][2] + bs;
        }
        if (o0 + 1 < 18) {
            float bs = ob[o0 + 1];
            float* pl = g_off + bb + (size_t)(o0 + 1) * 16384;
            pl[yA * 128 + xA]       = acc0[nt][1] + bs;
            pl[yA * 128 + xB]       = acc0[nt][3] + bs;
            pl[(yA + 1) * 128 + xA] = acc1[nt][1] + bs;
            pl[(yA + 1) * 128 + xB] = acc1[nt][3] + bs;
        }
    }
}

// ===================== SMEM layout main (float index) =====================
// smeta : 2304 x uint2 {packed(wy,wx), pos}                [0, 4608)
// xth   : 4 cpairs x 870 packed half2                      [4608, 8088)
// wh16  : 1280 x uint2                                     [8088, 10648)
#define SM_MT  0
#define SM_XT  4608
#define SM_WH  8088
#define SMEM_MAIN_BYTES (10648 * 4)

// ===================== stage 2: half2 gather + fp16 mma16 ==================
// Block 16x16 pixels (M=256), 256 threads = 8 warps; warp = 32 px (2 m16 tiles).
// N=64. K = 8ch/chunk x 10 taps (tap 9 = pad, W=0, A reused).
__global__ __launch_bounds__(256, 2) void deform_main_kernel(
    const float* __restrict__ x, const float* __restrict__ db,
    float* __restrict__ out)
{
    extern __shared__ __align__(16) float smf[];
    uint2*    smeta = (uint2*)(smf + SM_MT);    // 2304
    uint32_t* xth   = (uint32_t*)(smf + SM_XT); // 4 cpairs x 870
    uint2*    wh16  = (uint2*)(smf + SM_WH);    // [g][tig][gid][nt]

    int tid = threadIdx.x, w = tid >> 5, lane = tid & 31;
    int gid = lane >> 2, tig = lane & 3;
    int b = blockIdx.z, ty = blockIdx.y * 16, tx = blockIdx.x * 16;
    const float* xb = x + (size_t)b * 64 * 16384;

    // ---- prologue: per (tap,pixel) compact metadata ----
    for (int e = tid; e < 2304; e += 256) {
        int k = e >> 8, p = e & 255;
        int yy = ty + (p >> 4), xx = tx + (p & 15);
        float dy = g_off[((size_t)b * 18 + 2 * k) * 16384 + yy * 128 + xx];
        float dx = g_off[((size_t)b * 18 + 2 * k + 1) * 16384 + yy * 128 + xx];
        float py = (float)(yy + k / 3 - 1) + dy;
        float px = (float)(xx + k % 3 - 1) + dx;
        float fy = floorf(py), fx = floorf(px);
        float wy = py - fy, wx = px - fx;
        // clamp to [-2,128]: clamped region has all-invalid corners -> exact 0
        int iy = (int)fminf(fmaxf(fy, -2.f), 128.f);
        int ix = (int)fminf(fmaxf(fx, -2.f), 128.f);
        int ly = iy - (ty - 6), lx = ix - (tx - 6);
        int val;
        if ((unsigned)ly < 28u && (unsigned)lx < 29u)
            val = ly * 30 + lx;
        else
            val = (int)(0x80000000u | ((unsigned)(iy + 2) << 8) | (unsigned)(ix + 2));
        smeta[e] = make_uint2(packf16(make_float2(wy, wx)), (uint32_t)val);
    }

    float acc0[8][4], acc1[8][4];
#pragma unroll
    for (int n = 0; n < 8; n++)
#pragma unroll
        for (int i = 0; i < 4; i++) { acc0[n][i] = 0.f; acc1[n][i] = 0.f; }

    const int p0 = w * 32 + gid;

    for (int j = 0; j < 8; j++) {
        __syncthreads();
        const float* xc = xb + (size_t)j * 8 * 16384;
        // x tile: 4 channel pairs x 29x30 (halo 6), packed half2
        for (int t = tid; t < 3480; t += 256) {
            int cp = t / 870, pos = t - cp * 870;
            int rr = pos / 30, cl = pos - rr * 30;
            int gy = ty - 6 + rr, gx = tx - 6 + cl;
            float2 v = make_float2(0.f, 0.f);
            if ((unsigned)gy < 128u && (unsigned)gx < 128u) {
                const float* s = xc + 2 * cp * 16384 + gy * 128 + gx;
                v.x = s[0];
                v.y = s[16384];
            }
            xth[t] = packf16(v);
        }
        {
            const uint4* src = (const uint4*)(g_wh16 + j * 1280);
            uint4* dst = (uint4*)wh16;
            for (int t = tid; t < 640; t += 256) dst[t] = src[t];
        }
        __syncthreads();

        const uint32_t* xtc = xth + tig * 870;
        const float* xg0 = xc + (size_t)(2 * tig) * 16384;
        const float* xg1 = xg0 + 16384;

#pragma unroll
        for (int g = 0; g < 5; g++) {
            int ib0 = (2 * g) * 256 + p0;
            uint32_t a0  = bs2h(xtc, xg0, xg1, smeta[ib0]);
            uint32_t a1  = bs2h(xtc, xg0, xg1, smeta[ib0 + 8]);
            uint32_t a0b = bs2h(xtc, xg0, xg1, smeta[ib0 + 16]);
            uint32_t a1b = bs2h(xtc, xg0, xg1, smeta[ib0 + 24]);
            uint32_t a2, a3, a2b, a3b;
            if (g < 4) {
                int ib1 = ib0 + 256;
                a2  = bs2h(xtc, xg0, xg1, smeta[ib1]);
                a3  = bs2h(xtc, xg0, xg1, smeta[ib1 + 8]);
                a2b = bs2h(xtc, xg0, xg1, smeta[ib1 + 16]);
                a3b = bs2h(xtc, xg0, xg1, smeta[ib1 + 24]);
            } else {               // pad tap: W=0, any finite A contributes 0
                a2 = a0; a3 = a1; a2b = a0b; a3b = a1b;
            }

            const uint4* Bp = (const uint4*)(wh16 + ((g * 4 + tig) * 8 + gid) * 8);
            uint4 q0 = Bp[0], q1 = Bp[1], q2 = Bp[2], q3 = Bp[3];

            mma16(acc0[0], a0, a1, a2, a3, q0.x, q0.y);
            mma16(acc1[0], a0b, a1b, a2b, a3b, q0.x, q0.y);
            mma16(acc0[1], a0, a1, a2, a3, q0.z, q0.w);
            mma16(acc1[1], a0b, a1b, a2b, a3b, q0.z, q0.w);
            mma16(acc0[2], a0, a1, a2, a3, q1.x, q1.y);
            mma16(acc1[2], a0b, a1b, a2b, a3b, q1.x, q1.y);
            mma16(acc0[3], a0, a1, a2, a3, q1.z, q1.w);
            mma16(acc1[3], a0b, a1b, a2b, a3b, q1.z, q1.w);
            mma16(acc0[4], a0, a1, a2, a3, q2.x, q2.y);
            mma16(acc1[4], a0b, a1b, a2b, a3b, q2.x, q2.y);
            mma16(acc0[5], a0, a1, a2, a3, q2.z, q2.w);
            mma16(acc1[5], a0b, a1b, a2b, a3b, q2.z, q2.w);
            mma16(acc0[6], a0, a1, a2, a3, q3.x, q3.y);
            mma16(acc1[6], a0b, a1b, a2b, a3b, q3.x, q3.y);
            mma16(acc0[7], a0, a1, a2, a3, q3.z, q3.w);
            mma16(acc1[7], a0b, a1b, a2b, a3b, q3.z, q3.w);
        }
    }

    // ---- epilogue: bias + relu ----
    int yA = ty + 2 * w, xA = tx + gid, xB = xA + 8;
    float* obp = out + (size_t)b * 64 * 16384;
#pragma unroll
    for (int nt = 0; nt < 8; nt++) {
        int o0 = nt * 8 + 2 * tig;
        float bs0 = db[o0], bs1 = db[o0 + 1];
        float* pl0 = obp + (size_t)o0 * 16384;
        float* pl1 = pl0 + 16384;
        pl0[yA * 128 + xA]       = fmaxf(acc0[nt][0] + bs0, 0.f);
        pl1[yA * 128 + xA]       = fmaxf(acc0[nt][1] + bs1, 0.f);
        pl0[yA * 128 + xB]       = fmaxf(acc0[nt][2] + bs0, 0.f);
        pl1[yA * 128 + xB]       = fmaxf(acc0[nt][3] + bs1, 0.f);
        pl0[(yA + 1) * 128 + xA] = fmaxf(acc1[nt][0] + bs0, 0.f);
        pl1[(yA + 1) * 128 + xA] = fmaxf(acc1[nt][1] + bs1, 0.f);
        pl0[(yA + 1) * 128 + xB] = fmaxf(acc1[nt][2] + bs0, 0.f);
        pl1[(yA + 1) * 128 + xB] = fmaxf(acc1[nt][3] + bs1, 0.f);
    }
}

// ===================== launch =====================
extern "C" void kernel_launch(void* const* d_in, const int* in_sizes, int n_in,
                              void* d_out, int out_size) {
    const float* x        = (const float*)d_in[0];  // (8,64,128,128)
    const float* offset_w = (const float*)d_in[1];  // (18,64,3,3)
    const float* offset_b = (const float*)d_in[2];  // (18,)
    const float* deform_w = (const float*)d_in[3];  // (64,64,3,3)
    const float* deform_b = (const float*)d_in[4];  // (64,)
    float* out = (float*)d_out;                     // (8,64,128,128)

    cudaFuncSetAttribute(deform_main_kernel,
                         cudaFuncAttributeMaxDynamicSharedMemorySize,
                         SMEM_MAIN_BYTES);

    wprep_kernel<<<144, 256>>>(deform_w, offset_w);
    offconv_kernel<<<dim3(8, 8, 8), 256>>>(x, offset_b);
    deform_main_kernel<<<dim3(8, 8, 8), 256, SMEM_MAIN_BYTES>>>(x, deform_b, out);
}

// round 11
// speedup vs baseline: 1.4858x; 1.1533x over previous
#include <cuda_runtime.h>
#include <cuda_fp16.h>
#include <cstdint>

// ===================== device scratch (no allocation) =====================
__device__ float g_off[8 * 18 * 128 * 128];   // offset conv output
__device__ uint2 g_w16m[4 * 9 * 4 * 8 * 8];   // main W fp16: [j][t][tig][gid][nt]
__device__ float g_owhi[8 * 72 * 32];         // offset W tf32: [j][kk][gid*4+nt]

// ===================== helpers =====================
__device__ __forceinline__ uint32_t f2tf32(float f) {
    uint32_t r;
    asm("cvt.rna.tf32.f32 %0, %1;" : "=r"(r) : "f"(f));
    return r;
}
__device__ __forceinline__ uint32_t packf16(float2 s) {
    uint32_t r;   // lo half = s.x
    asm("cvt.rn.f16x2.f32 %0, %1, %2;" : "=r"(r) : "f"(s.y), "f"(s.x));
    return r;
}
__device__ __forceinline__ uint32_t hsub2(uint32_t a, uint32_t b) {
    uint32_t d;
    asm("sub.rn.f16x2 %0, %1, %2;" : "=r"(d) : "r"(a), "r"(b));
    return d;
}
__device__ __forceinline__ uint32_t hfma2(uint32_t a, uint32_t b, uint32_t c) {
    uint32_t d;
    asm("fma.rn.f16x2 %0, %1, %2, %3;" : "=r"(d) : "r"(a), "r"(b), "r"(c));
    return d;
}
__device__ __forceinline__ uint32_t duplo(uint32_t a) {   // low half -> both
    uint32_t d;
    asm("prmt.b32 %0, %1, %1, 0x1010;" : "=r"(d) : "r"(a));
    return d;
}
__device__ __forceinline__ uint32_t duphi(uint32_t a) {   // high half -> both
    uint32_t d;
    asm("prmt.b32 %0, %1, %1, 0x3232;" : "=r"(d) : "r"(a));
    return d;
}
__device__ __forceinline__ float h2lof(uint32_t h) {
    __half2 v = *(__half2*)&h;
    return __low2float(v);
}
__device__ __forceinline__ void mma8(float* d,
                                     uint32_t a0, uint32_t a1, uint32_t a2, uint32_t a3,
                                     uint32_t b0, uint32_t b1) {
    asm volatile(
        "mma.sync.aligned.m16n8k8.row.col.f32.tf32.tf32.f32 "
        "{%0,%1,%2,%3}, {%4,%5,%6,%7}, {%8,%9}, {%0,%1,%2,%3};"
        : "+f"(d[0]), "+f"(d[1]), "+f"(d[2]), "+f"(d[3])
        : "r"(a0), "r"(a1), "r"(a2), "r"(a3), "r"(b0), "r"(b1));
}
__device__ __forceinline__ void mma16(float* d,
                                      uint32_t a0, uint32_t a1, uint32_t a2, uint32_t a3,
                                      uint32_t b0, uint32_t b1) {
    asm volatile(
        "mma.sync.aligned.m16n8k16.row.col.f32.f16.f16.f32 "
        "{%0,%1,%2,%3}, {%4,%5,%6,%7}, {%8,%9}, {%0,%1,%2,%3};"
        : "+f"(d[0]), "+f"(d[1]), "+f"(d[2]), "+f"(d[3])
        : "r"(a0), "r"(a1), "r"(a2), "r"(a3), "r"(b0), "r"(b1));
}

// bilinear sample of a channel QUAD (uint2 = 2x half2), interpolation form.
// m.x = packed half2 (wy lo, wx hi); m.y = tile offset or fallback coords.
// Returns uint2: .x = ch pair (4q,4q+1)  -> a0/a1 slots, .y = (4q+2,4q+3) -> a2/a3.
__device__ __forceinline__ uint2 bsq(const uint2* __restrict__ xt_q,
                                     const float* __restrict__ xgq,
                                     uint2 m) {
    int val = (int)m.y;
    uint32_t wyd = duplo(m.x), wxd = duphi(m.x);
    if (val >= 0) {
        uint2 c0 = xt_q[val], c1 = xt_q[val + 1];
        uint2 c2 = xt_q[val + 30], c3 = xt_q[val + 31];
        uint32_t rx0 = hfma2(hsub2(c1.x, c0.x), wxd, c0.x);
        uint32_t rx1 = hfma2(hsub2(c3.x, c2.x), wxd, c2.x);
        uint32_t ry0 = hfma2(hsub2(c1.y, c0.y), wxd, c0.y);
        uint32_t ry1 = hfma2(hsub2(c3.y, c2.y), wxd, c2.y);
        uint2 r;
        r.x = hfma2(hsub2(rx1, rx0), wyd, rx0);
        r.y = hfma2(hsub2(ry1, ry0), wyd, ry0);
        return r;
    }
    // rare fallback: fp32 masked global bilinear on 4 channels
    float wy = h2lof(wyd), wx = h2lof(wxd);
    float oy = 1.f - wy, ox = 1.f - wx;
    float w00 = oy * ox, w01 = oy * wx, w10 = wy * ox, w11 = wy * wx;
    int iy = ((val >> 8) & 0xff) - 2;
    int ix = (val & 0xff) - 2;
    bool m00 = ((unsigned)iy < 128u) & ((unsigned)ix < 128u);
    bool m01 = ((unsigned)iy < 128u) & ((unsigned)(ix + 1) < 128u);
    bool m10 = ((unsigned)(iy + 1) < 128u) & ((unsigned)ix < 128u);
    bool m11 = ((unsigned)(iy + 1) < 128u) & ((unsigned)(ix + 1) < 128u);
    int i00 = iy * 128 + ix;
    float v[4];
#pragma unroll
    for (int c = 0; c < 4; c++) {
        const float* g = xgq + c * 16384;
        v[c] = w00 * (m00 ? g[i00] : 0.f) + w01 * (m01 ? g[i00 + 1] : 0.f)
             + w10 * (m10 ? g[i00 + 128] : 0.f) + w11 * (m11 ? g[i00 + 129] : 0.f);
    }
    uint2 r;
    r.x = packf16(make_float2(v[0], v[1]));
    r.y = packf16(make_float2(v[2], v[3]));
    return r;
}

// ===================== prep: weight layouts =====================
__global__ void wprep_kernel(const float* __restrict__ dw,
                             const float* __restrict__ ow) {
    int i = blockIdx.x * 256 + threadIdx.x;
    if (i < 9216) {            // main W: [j][t][tig][gid][nt], quad-channel slots
        int j = i / 2304, r = i - j * 2304;
        int t = r >> 8, r2 = r & 255;
        int tg = r2 >> 6, r3 = r2 & 63;
        int gd = r3 >> 3, nt = r3 & 7;
        int o = nt * 8 + gd;
        int c0 = j * 16 + 4 * tg;
        __half2 h0 = __floats2half2_rn(dw[o * 576 + c0 * 9 + t],
                                       dw[o * 576 + (c0 + 1) * 9 + t]);
        __half2 h1 = __floats2half2_rn(dw[o * 576 + (c0 + 2) * 9 + t],
                                       dw[o * 576 + (c0 + 3) * 9 + t]);
        uint2 v;
        v.x = *(uint32_t*)&h0;
        v.y = *(uint32_t*)&h1;
        g_w16m[i] = v;
    }
    if (i < 18432) {           // offset W tf32: [j][kk][gid*4+nt]
        int j = i / 2304, r = i - j * 2304;
        int kk = r >> 5, col = r & 31;
        int tap = kk >> 3, s = kk & 7;
        int c = j * 8 + 2 * (s & 3) + (s >> 2);
        int nt = col & 3, g = col >> 2;
        int o = nt * 8 + g;
        float wv = (nt < 3 && o < 18) ? ow[o * 576 + c * 9 + tap] : 0.f;
        g_owhi[i] = __uint_as_float(f2tf32(wv));
    }
}

// ===================== stage 1: offset conv via mma (tf32) =====================
__global__ __launch_bounds__(256, 2) void offconv_kernel(
    const float* __restrict__ x, const float* __restrict__ ob)
{
    __shared__ float2 xt2[1296];        // 4 cpairs x 18x18 (halo 1)
    __shared__ float wh[2304];          // [kk][32]

    int tid = threadIdx.x, w = tid >> 5, lane = tid & 31;
    int gid = lane >> 2, tig = lane & 3;
    int b = blockIdx.z, ty = blockIdx.y * 16, tx = blockIdx.x * 16;
    const float* xb = x + (size_t)b * 64 * 16384;

    float acc0[3][4], acc1[3][4];
#pragma unroll
    for (int n = 0; n < 3; n++)
#pragma unroll
        for (int i = 0; i < 4; i++) { acc0[n][i] = 0.f; acc1[n][i] = 0.f; }

    for (int j = 0; j < 8; j++) {
        __syncthreads();
        const float* xc = xb + (size_t)j * 8 * 16384;
        for (int t = tid; t < 1296; t += 256) {
            int cp = t / 324, pos = t - cp * 324;
            int rr = pos / 18, cl = pos - rr * 18;
            int gy = ty - 1 + rr, gx = tx - 1 + cl;
            float2 v = make_float2(0.f, 0.f);
            if ((unsigned)gy < 128u && (unsigned)gx < 128u) {
                const float* s = xc + 2 * cp * 16384 + gy * 128 + gx;
                v.x = __uint_as_float(f2tf32(s[0]));
                v.y = __uint_as_float(f2tf32(s[16384]));
            }
            xt2[t] = v;
        }
        for (int t = tid; t < 2304; t += 256) wh[t] = g_owhi[j * 2304 + t];
        __syncthreads();

#pragma unroll
        for (int kt = 0; kt < 9; kt++) {
            int dty = kt / 3, dtx = kt - dty * 3;
            const float2* ap = xt2 + tig * 324 + (2 * w + dty) * 18 + gid + dtx;
            float2 f0 = ap[0], f1 = ap[8], f2v = ap[18], f3 = ap[26];
            float4 bA = *(const float4*)(wh + (kt * 8 + tig) * 32 + gid * 4);
            float4 bB = *(const float4*)(wh + (kt * 8 + tig + 4) * 32 + gid * 4);
            uint32_t a0 = __float_as_uint(f0.x), a1 = __float_as_uint(f1.x);
            uint32_t a2 = __float_as_uint(f0.y), a3 = __float_as_uint(f1.y);
            uint32_t g0 = __float_as_uint(f2v.x), g1 = __float_as_uint(f3.x);
            uint32_t g2 = __float_as_uint(f2v.y), g3 = __float_as_uint(f3.y);
            mma8(acc0[0], a0, a1, a2, a3, __float_as_uint(bA.x), __float_as_uint(bB.x));
            mma8(acc0[1], a0, a1, a2, a3, __float_as_uint(bA.y), __float_as_uint(bB.y));
            mma8(acc0[2], a0, a1, a2, a3, __float_as_uint(bA.z), __float_as_uint(bB.z));
            mma8(acc1[0], g0, g1, g2, g3, __float_as_uint(bA.x), __float_as_uint(bB.x));
            mma8(acc1[1], g0, g1, g2, g3, __float_as_uint(bA.y), __float_as_uint(bB.y));
            mma8(acc1[2], g0, g1, g2, g3, __float_as_uint(bA.z), __float_as_uint(bB.z));
        }
    }

    int yA = ty + 2 * w, xA = tx + gid, xB = xA + 8;
    size_t bb = (size_t)b * 18 * 16384;
#pragma unroll
    for (int nt = 0; nt < 3; nt++) {
        int o0 = nt * 8 + 2 * tig;
        if (o0 < 18) {
            float bs = ob[o0];
            float* pl = g_off + bb + (size_t)o0 * 16384;
            pl[yA * 128 + xA]       = acc0[nt][0] + bs;
            pl[yA * 128 + xB]       = acc0[nt][2] + bs;
            pl[(yA + 1) * 128 + xA] = acc1[nt][0] + bs;
            pl[(yA + 1) * 128 + xB] = acc1[nt][2] + bs;
        }
        if (o0 + 1 < 18) {
            float bs = ob[o0 + 1];
            float* pl = g_off + bb + (size_t)(o0 + 1) * 16384;
            pl[yA * 128 + xA]       = acc0[nt][1] + bs;
            pl[yA * 128 + xB]       = acc0[nt][3] + bs;
            pl[(yA + 1) * 128 + xA] = acc1[nt][1] + bs;
            pl[(yA + 1) * 128 + xB] = acc1[nt][3] + bs;
        }
    }
}

// ===================== SMEM layout main (float index) =====================
// smeta : 2304 x uint2 {packed(wy,wx), pos}                [0, 4608)
// xtq   : 4 quads x 870 uint2 (4ch packed)                 [4608, 11568)
// whs   : 2304 x uint2  [t][tig][gid][nt]                  [11568, 16176)
#define SM_MT  0
#define SM_XT  4608
#define SM_WH  11568
#define SMEM_MAIN_BYTES (16176 * 4)

// ===================== stage 2: quad gather + fp16 mma16 ===================
// Block 16x16 pixels (M=256), 256 threads = 8 warps; warp = 32 px (2 m16 tiles).
// N=64. K = 16 channels x 1 tap per mma16; 4 chunks of 16 channels x 9 taps.
__global__ __launch_bounds__(256, 2) void deform_main_kernel(
    const float* __restrict__ x, const float* __restrict__ db,
    float* __restrict__ out)
{
    extern __shared__ __align__(16) float smf[];
    uint2* smeta = (uint2*)(smf + SM_MT);   // 2304
    uint2* xtq   = (uint2*)(smf + SM_XT);   // 4 quads x 870
    uint2* whs   = (uint2*)(smf + SM_WH);   // 2304

    int tid = threadIdx.x, w = tid >> 5, lane = tid & 31;
    int gid = lane >> 2, tig = lane & 3;
    int b = blockIdx.z, ty = blockIdx.y * 16, tx = blockIdx.x * 16;
    const float* xb = x + (size_t)b * 64 * 16384;

    // ---- prologue: per (tap,pixel) compact metadata ----
    for (int e = tid; e < 2304; e += 256) {
        int k = e >> 8, p = e & 255;
        int yy = ty + (p >> 4), xx = tx + (p & 15);
        float dy = g_off[((size_t)b * 18 + 2 * k) * 16384 + yy * 128 + xx];
        float dx = g_off[((size_t)b * 18 + 2 * k + 1) * 16384 + yy * 128 + xx];
        float py = (float)(yy + k / 3 - 1) + dy;
        float px = (float)(xx + k % 3 - 1) + dx;
        float fy = floorf(py), fx = floorf(px);
        float wy = py - fy, wx = px - fx;
        // clamp to [-2,128]: clamped region has all-invalid corners -> exact 0
        int iy = (int)fminf(fmaxf(fy, -2.f), 128.f);
        int ix = (int)fminf(fmaxf(fx, -2.f), 128.f);
        int ly = iy - (ty - 6), lx = ix - (tx - 6);
        int val;
        if ((unsigned)ly < 28u && (unsigned)lx < 29u)
            val = ly * 30 + lx;
        else
            val = (int)(0x80000000u | ((unsigned)(iy + 2) << 8) | (unsigned)(ix + 2));
        smeta[e] = make_uint2(packf16(make_float2(wy, wx)), (uint32_t)val);
    }

    float acc0[8][4], acc1[8][4];
#pragma unroll
    for (int n = 0; n < 8; n++)
#pragma unroll
        for (int i = 0; i < 4; i++) { acc0[n][i] = 0.f; acc1[n][i] = 0.f; }

    const int p0 = w * 32 + gid;

    for (int j = 0; j < 4; j++) {
        __syncthreads();
        const float* xc = xb + (size_t)j * 16 * 16384;
        // x tile: 4 channel quads x 29x30 (halo 6), packed 2x half2
        for (int t = tid; t < 3480; t += 256) {
            int q = t / 870, pos = t - q * 870;
            int rr = pos / 30, cl = pos - rr * 30;
            int gy = ty - 6 + rr, gx = tx - 6 + cl;
            uint2 v = make_uint2(0u, 0u);
            if ((unsigned)gy < 128u && (unsigned)gx < 128u) {
                const float* s = xc + 4 * q * 16384 + gy * 128 + gx;
                v.x = packf16(make_float2(s[0], s[16384]));
                v.y = packf16(make_float2(s[2 * 16384], s[3 * 16384]));
            }
            xtq[t] = v;
        }
        {
            const uint4* src = (const uint4*)(g_w16m + j * 2304);
            uint4* dst = (uint4*)whs;
            for (int t = tid; t < 1152; t += 256) dst[t] = src[t];
        }
        __syncthreads();

        const uint2* xq = xtq + tig * 870;
        const float* xgq = xc + (size_t)(4 * tig) * 16384;

#pragma unroll
        for (int t = 0; t < 9; t++) {
            int ib = t * 256 + p0;
            uint2 A0 = bsq(xq, xgq, smeta[ib]);        // m tile 0, row gid
            uint2 A1 = bsq(xq, xgq, smeta[ib + 8]);    // m tile 0, row gid+8
            uint2 A2 = bsq(xq, xgq, smeta[ib + 16]);   // m tile 1, row gid
            uint2 A3 = bsq(xq, xgq, smeta[ib + 24]);   // m tile 1, row gid+8

            const uint4* Bp = (const uint4*)(whs + ((t * 4 + tig) * 8 + gid) * 8);
            uint4 q0 = Bp[0], q1 = Bp[1], q2 = Bp[2], q3 = Bp[3];

            mma16(acc0[0], A0.x, A1.x, A0.y, A1.y, q0.x, q0.y);
            mma16(acc1[0], A2.x, A3.x, A2.y, A3.y, q0.x, q0.y);
            mma16(acc0[1], A0.x, A1.x, A0.y, A1.y, q0.z, q0.w);
            mma16(acc1[1], A2.x, A3.x, A2.y, A3.y, q0.z, q0.w);
            mma16(acc0[2], A0.x, A1.x, A0.y, A1.y, q1.x, q1.y);
            mma16(acc1[2], A2.x, A3.x, A2.y, A3.y, q1.x, q1.y);
            mma16(acc0[3], A0.x, A1.x, A0.y, A1.y, q1.z, q1.w);
            mma16(acc1[3], A2.x, A3.x, A2.y, A3.y, q1.z, q1.w);
            mma16(acc0[4], A0.x, A1.x, A0.y, A1.y, q2.x, q2.y);
            mma16(acc1[4], A2.x, A3.x, A2.y, A3.y, q2.x, q2.y);
            mma16(acc0[5], A0.x, A1.x, A0.y, A1.y, q2.z, q2.w);
            mma16(acc1[5], A2.x, A3.x, A2.y, A3.y, q2.z, q2.w);
            mma16(acc0[6], A0.x, A1.x, A0.y, A1.y, q3.x, q3.y);
            mma16(acc1[6], A2.x, A3.x, A2.y, A3.y, q3.x, q3.y);
            mma16(acc0[7], A0.x, A1.x, A0.y, A1.y, q3.z, q3.w);
            mma16(acc1[7], A2.x, A3.x, A2.y, A3.y, q3.z, q3.w);
        }
    }

    // ---- epilogue: bias + relu ----
    int yA = ty + 2 * w, xA = tx + gid, xB = xA + 8;
    float* obp = out + (size_t)b * 64 * 16384;
#pragma unroll
    for (int nt = 0; nt < 8; nt++) {
        int o0 = nt * 8 + 2 * tig;
        float bs0 = db[o0], bs1 = db[o0 + 1];
        float* pl0 = obp + (size_t)o0 * 16384;
        float* pl1 = pl0 + 16384;
        pl0[yA * 128 + xA]       = fmaxf(acc0[nt][0] + bs0, 0.f);
        pl1[yA * 128 + xA]       = fmaxf(acc0[nt][1] + bs1, 0.f);
        pl0[yA * 128 + xB]       = fmaxf(acc0[nt][2] + bs0, 0.f);
        pl1[yA * 128 + xB]       = fmaxf(acc0[nt][3] + bs1, 0.f);
        pl0[(yA + 1) * 128 + xA] = fmaxf(acc1[nt][0] + bs0, 0.f);
        pl1[(yA + 1) * 128 + xA] = fmaxf(acc1[nt][1] + bs1, 0.f);
        pl0[(yA + 1) * 128 + xB] = fmaxf(acc1[nt][2] + bs0, 0.f);
        pl1[(yA + 1) * 128 + xB] = fmaxf(acc1[nt][3] + bs1, 0.f);
    }
}

// ===================== launch =====================
extern "C" void kernel_launch(void* const* d_in, const int* in_sizes, int n_in,
                              void* d_out, int out_size) {
    const float* x        = (const float*)d_in[0];  // (8,64,128,128)
    const float* offset_w = (const float*)d_in[1];  // (18,64,3,3)
    const float* offset_b = (const float*)d_in[2];  // (18,)
    const float* deform_w = (const float*)d_in[3];  // (64,64,3,3)
    const float* deform_b = (const float*)d_in[4];  // (64,)
    float* out = (float*)d_out;                     // (8,64,128,128)

    cudaFuncSetAttribute(deform_main_kernel,
                         cudaFuncAttributeMaxDynamicSharedMemorySize,
                         SMEM_MAIN_BYTES);

    wprep_kernel<<<144, 256>>>(deform_w, offset_w);
    offconv_kernel<<<dim3(8, 8, 8), 256>>>(x, offset_b);
    deform_main_kernel<<<dim3(8, 8, 8), 256, SMEM_MAIN_BYTES>>>(x, deform_b, out);
}

// round 12
// speedup vs baseline: 1.8157x; 1.2221x over previous
#include <cuda_runtime.h>
#include <cuda_fp16.h>
#include <cstdint>

// ===================== device scratch (no allocation) =====================
__device__ float g_off[8 * 18 * 128 * 128];   // offset conv output
__device__ uint2 g_w16m[4 * 9 * 4 * 8 * 8];   // main W fp16: [j][t][tig][gid][nt8]
__device__ uint2 g_ow16[4 * 9 * 4 * 8 * 4];   // offset W fp16: [j][t][tig][gid][nt4]

// ===================== helpers =====================
__device__ __forceinline__ uint32_t packf16(float2 s) {
    uint32_t r;   // lo half = s.x
    asm("cvt.rn.f16x2.f32 %0, %1, %2;" : "=r"(r) : "f"(s.y), "f"(s.x));
    return r;
}
__device__ __forceinline__ uint32_t hsub2(uint32_t a, uint32_t b) {
    uint32_t d;
    asm("sub.rn.f16x2 %0, %1, %2;" : "=r"(d) : "r"(a), "r"(b));
    return d;
}
__device__ __forceinline__ uint32_t hfma2(uint32_t a, uint32_t b, uint32_t c) {
    uint32_t d;
    asm("fma.rn.f16x2 %0, %1, %2, %3;" : "=r"(d) : "r"(a), "r"(b), "r"(c));
    return d;
}
__device__ __forceinline__ uint32_t duplo(uint32_t a) {   // low half -> both
    uint32_t d;
    asm("prmt.b32 %0, %1, %1, 0x1010;" : "=r"(d) : "r"(a));
    return d;
}
__device__ __forceinline__ uint32_t duphi(uint32_t a) {   // high half -> both
    uint32_t d;
    asm("prmt.b32 %0, %1, %1, 0x3232;" : "=r"(d) : "r"(a));
    return d;
}
__device__ __forceinline__ float h2lof(uint32_t h) {
    __half2 v = *(__half2*)&h;
    return __low2float(v);
}
__device__ __forceinline__ void mma16(float* d,
                                      uint32_t a0, uint32_t a1, uint32_t a2, uint32_t a3,
                                      uint32_t b0, uint32_t b1) {
    asm volatile(
        "mma.sync.aligned.m16n8k16.row.col.f32.f16.f16.f32 "
        "{%0,%1,%2,%3}, {%4,%5,%6,%7}, {%8,%9}, {%0,%1,%2,%3};"
        : "+f"(d[0]), "+f"(d[1]), "+f"(d[2]), "+f"(d[3])
        : "r"(a0), "r"(a1), "r"(a2), "r"(a3), "r"(b0), "r"(b1));
}

// bilinear sample of a channel QUAD (uint2 = 2x half2), interpolation form.
__device__ __forceinline__ uint2 bsq(const uint2* __restrict__ xt_q,
                                     const float* __restrict__ xgq,
                                     uint2 m) {
    int val = (int)m.y;
    uint32_t wyd = duplo(m.x), wxd = duphi(m.x);
    if (val >= 0) {
        uint2 c0 = xt_q[val], c1 = xt_q[val + 1];
        uint2 c2 = xt_q[val + 30], c3 = xt_q[val + 31];
        uint32_t rx0 = hfma2(hsub2(c1.x, c0.x), wxd, c0.x);
        uint32_t rx1 = hfma2(hsub2(c3.x, c2.x), wxd, c2.x);
        uint32_t ry0 = hfma2(hsub2(c1.y, c0.y), wxd, c0.y);
        uint32_t ry1 = hfma2(hsub2(c3.y, c2.y), wxd, c2.y);
        uint2 r;
        r.x = hfma2(hsub2(rx1, rx0), wyd, rx0);
        r.y = hfma2(hsub2(ry1, ry0), wyd, ry0);
        return r;
    }
    // rare fallback: fp32 masked global bilinear on 4 channels
    float wy = h2lof(wyd), wx = h2lof(wxd);
    float oy = 1.f - wy, ox = 1.f - wx;
    float w00 = oy * ox, w01 = oy * wx, w10 = wy * ox, w11 = wy * wx;
    int iy = ((val >> 8) & 0xff) - 2;
    int ix = (val & 0xff) - 2;
    bool m00 = ((unsigned)iy < 128u) & ((unsigned)ix < 128u);
    bool m01 = ((unsigned)iy < 128u) & ((unsigned)(ix + 1) < 128u);
    bool m10 = ((unsigned)(iy + 1) < 128u) & ((unsigned)ix < 128u);
    bool m11 = ((unsigned)(iy + 1) < 128u) & ((unsigned)(ix + 1) < 128u);
    int i00 = iy * 128 + ix;
    float v[4];
#pragma unroll
    for (int c = 0; c < 4; c++) {
        const float* g = xgq + c * 16384;
        v[c] = w00 * (m00 ? g[i00] : 0.f) + w01 * (m01 ? g[i00 + 1] : 0.f)
             + w10 * (m10 ? g[i00 + 128] : 0.f) + w11 * (m11 ? g[i00 + 129] : 0.f);
    }
    uint2 r;
    r.x = packf16(make_float2(v[0], v[1]));
    r.y = packf16(make_float2(v[2], v[3]));
    return r;
}

// ===================== prep: weight layouts =====================
__global__ void wprep_kernel(const float* __restrict__ dw,
                             const float* __restrict__ ow) {
    int i = blockIdx.x * 256 + threadIdx.x;
    if (i < 9216) {            // main W: [j][t][tig][gid][nt], quad-channel slots
        int j = i / 2304, r = i - j * 2304;
        int t = r >> 8, r2 = r & 255;
        int tg = r2 >> 6, r3 = r2 & 63;
        int gd = r3 >> 3, nt = r3 & 7;
        int o = nt * 8 + gd;
        int c0 = j * 16 + 4 * tg;
        __half2 h0 = __floats2half2_rn(dw[o * 576 + c0 * 9 + t],
                                       dw[o * 576 + (c0 + 1) * 9 + t]);
        __half2 h1 = __floats2half2_rn(dw[o * 576 + (c0 + 2) * 9 + t],
                                       dw[o * 576 + (c0 + 3) * 9 + t]);
        uint2 v;
        v.x = *(uint32_t*)&h0;
        v.y = *(uint32_t*)&h1;
        g_w16m[i] = v;
    }
    if (i < 4608) {            // offset W: [j][t][tig][gid][nt4], o = nt*8+gid
        int j = i / 1152, r = i - j * 1152;
        int t = r >> 7, r2 = r & 127;
        int tg = r2 >> 5, r3 = r2 & 31;
        int gd = r3 >> 2, nt = r3 & 3;
        int o = nt * 8 + gd;
        int c0 = j * 16 + 4 * tg;
        float w0 = 0.f, w1 = 0.f, w2 = 0.f, w3 = 0.f;
        if (o < 18) {
            w0 = ow[o * 576 + c0 * 9 + t];
            w1 = ow[o * 576 + (c0 + 1) * 9 + t];
            w2 = ow[o * 576 + (c0 + 2) * 9 + t];
            w3 = ow[o * 576 + (c0 + 3) * 9 + t];
        }
        uint2 v;
        v.x = packf16(make_float2(w0, w1));
        v.y = packf16(make_float2(w2, w3));
        g_ow16[i] = v;
    }
}

// ===================== stage 1: offset conv, quad fp16 mma16 =====================
// Block 16x16 px, 8 warps; warp = px rows {2w, 2w+1}. N=24 (18 used), K=16ch x tap.
__global__ __launch_bounds__(256, 2) void offconv_kernel(
    const float* __restrict__ x, const float* __restrict__ ob)
{
    __shared__ uint2 xtq[1296];         // 4 quads x 18x18 (halo 1)
    __shared__ uint2 wh[1152];          // [t][tig][gid][nt4]

    int tid = threadIdx.x, w = tid >> 5, lane = tid & 31;
    int gid = lane >> 2, tig = lane & 3;
    int b = blockIdx.z, ty = blockIdx.y * 16, tx = blockIdx.x * 16;
    const float* xb = x + (size_t)b * 64 * 16384;

    float acc0[3][4], acc1[3][4];
#pragma unroll
    for (int n = 0; n < 3; n++)
#pragma unroll
        for (int i = 0; i < 4; i++) { acc0[n][i] = 0.f; acc1[n][i] = 0.f; }

    for (int j = 0; j < 4; j++) {
        __syncthreads();
        const float* xc = xb + (size_t)j * 16 * 16384;
        for (int t = tid; t < 1296; t += 256) {
            int q = t / 324, pos = t - q * 324;
            int rr = pos / 18, cl = pos - rr * 18;
            int gy = ty - 1 + rr, gx = tx - 1 + cl;
            uint2 v = make_uint2(0u, 0u);
            if ((unsigned)gy < 128u && (unsigned)gx < 128u) {
                const float* s = xc + 4 * q * 16384 + gy * 128 + gx;
                v.x = packf16(make_float2(s[0], s[16384]));
                v.y = packf16(make_float2(s[2 * 16384], s[3 * 16384]));
            }
            xtq[t] = v;
        }
        for (int t = tid; t < 1152; t += 256) wh[t] = g_ow16[j * 1152 + t];
        __syncthreads();

#pragma unroll
        for (int t9 = 0; t9 < 9; t9++) {
            int dty = t9 / 3, dtx = t9 - dty * 3;
            const uint2* ap = xtq + tig * 324 + (2 * w + dty) * 18 + gid + dtx;
            uint2 A0 = ap[0], A1 = ap[8], A2 = ap[18], A3 = ap[26];

            const uint2* Bp = wh + ((t9 * 4 + tig) * 8 + gid) * 4;
            uint4 q01 = *(const uint4*)Bp;      // nt0 (x,y), nt1 (z,w)
            uint2 q2 = Bp[2];                   // nt2

            mma16(acc0[0], A0.x, A1.x, A0.y, A1.y, q01.x, q01.y);
            mma16(acc1[0], A2.x, A3.x, A2.y, A3.y, q01.x, q01.y);
            mma16(acc0[1], A0.x, A1.x, A0.y, A1.y, q01.z, q01.w);
            mma16(acc1[1], A2.x, A3.x, A2.y, A3.y, q01.z, q01.w);
            mma16(acc0[2], A0.x, A1.x, A0.y, A1.y, q2.x, q2.y);
            mma16(acc1[2], A2.x, A3.x, A2.y, A3.y, q2.x, q2.y);
        }
    }

    int yA = ty + 2 * w, xA = tx + gid, xB = xA + 8;
    size_t bb = (size_t)b * 18 * 16384;
#pragma unroll
    for (int nt = 0; nt < 3; nt++) {
        int o0 = nt * 8 + 2 * tig;
        if (o0 < 18) {
            float bs = ob[o0];
            float* pl = g_off + bb + (size_t)o0 * 16384;
            pl[yA * 128 + xA]       = acc0[nt][0] + bs;
            pl[yA * 128 + xB]       = acc0[nt][2] + bs;
            pl[(yA + 1) * 128 + xA] = acc1[nt][0] + bs;
            pl[(yA + 1) * 128 + xB] = acc1[nt][2] + bs;
        }
        if (o0 + 1 < 18) {
            float bs = ob[o0 + 1];
            float* pl = g_off + bb + (size_t)(o0 + 1) * 16384;
            pl[yA * 128 + xA]       = acc0[nt][1] + bs;
            pl[yA * 128 + xB]       = acc0[nt][3] + bs;
            pl[(yA + 1) * 128 + xA] = acc1[nt][1] + bs;
            pl[(yA + 1) * 128 + xB] = acc1[nt][3] + bs;
        }
    }
}

// ===================== SMEM layout main (float index) =====================
// smeta : 2304 x uint2 {packed(wy,wx), pos}                [0, 4608)
// xtq   : 4 quads x 870 uint2 (4ch packed)                 [4608, 11568)
// whs   : 2304 x uint2  [t][tig][gid][nt]                  [11568, 16176)
#define SM_MT  0
#define SM_XT  4608
#define SM_WH  11568
#define SMEM_MAIN_BYTES (16176 * 4)

// ===================== stage 2: quad gather + fp16 mma16 ===================
// Block 16x16 pixels (M=256), 256 threads = 8 warps; warp = 32 px (2 m16 tiles).
// N=64. K = 16 channels x 1 tap per mma16; 4 chunks of 16 channels x 9 taps.
__global__ __launch_bounds__(256, 2) void deform_main_kernel(
    const float* __restrict__ x, const float* __restrict__ db,
    float* __restrict__ out)
{
    extern __shared__ __align__(16) float smf[];
    uint2* smeta = (uint2*)(smf + SM_MT);   // 2304
    uint2* xtq   = (uint2*)(smf + SM_XT);   // 4 quads x 870
    uint2* whs   = (uint2*)(smf + SM_WH);   // 2304

    int tid = threadIdx.x, w = tid >> 5, lane = tid & 31;
    int gid = lane >> 2, tig = lane & 3;
    int b = blockIdx.z, ty = blockIdx.y * 16, tx = blockIdx.x * 16;
    const float* xb = x + (size_t)b * 64 * 16384;

    // ---- prologue: per (tap,pixel) compact metadata ----
    for (int e = tid; e < 2304; e += 256) {
        int k = e >> 8, p = e & 255;
        int yy = ty + (p >> 4), xx = tx + (p & 15);
        float dy = g_off[((size_t)b * 18 + 2 * k) * 16384 + yy * 128 + xx];
        float dx = g_off[((size_t)b * 18 + 2 * k + 1) * 16384 + yy * 128 + xx];
        float py = (float)(yy + k / 3 - 1) + dy;
        float px = (float)(xx + k % 3 - 1) + dx;
        float fy = floorf(py), fx = floorf(px);
        float wy = py - fy, wx = px - fx;
        // clamp to [-2,128]: clamped region has all-invalid corners -> exact 0
        int iy = (int)fminf(fmaxf(fy, -2.f), 128.f);
        int ix = (int)fminf(fmaxf(fx, -2.f), 128.f);
        int ly = iy - (ty - 6), lx = ix - (tx - 6);
        int val;
        if ((unsigned)ly < 28u && (unsigned)lx < 29u)
            val = ly * 30 + lx;
        else
            val = (int)(0x80000000u | ((unsigned)(iy + 2) << 8) | (unsigned)(ix + 2));
        smeta[e] = make_uint2(packf16(make_float2(wy, wx)), (uint32_t)val);
    }

    float acc0[8][4], acc1[8][4];
#pragma unroll
    for (int n = 0; n < 8; n++)
#pragma unroll
        for (int i = 0; i < 4; i++) { acc0[n][i] = 0.f; acc1[n][i] = 0.f; }

    const int p0 = w * 32 + gid;

    for (int j = 0; j < 4; j++) {
        __syncthreads();
        const float* xc = xb + (size_t)j * 16 * 16384;
        // x tile: 4 channel quads x 29x30 (halo 6), packed 2x half2
        for (int t = tid; t < 3480; t += 256) {
            int q = t / 870, pos = t - q * 870;
            int rr = pos / 30, cl = pos - rr * 30;
            int gy = ty - 6 + rr, gx = tx - 6 + cl;
            uint2 v = make_uint2(0u, 0u);
            if ((unsigned)gy < 128u && (unsigned)gx < 128u) {
                const float* s = xc + 4 * q * 16384 + gy * 128 + gx;
                v.x = packf16(make_float2(s[0], s[16384]));
                v.y = packf16(make_float2(s[2 * 16384], s[3 * 16384]));
            }
            xtq[t] = v;
        }
        {
            const uint4* src = (const uint4*)(g_w16m + j * 2304);
            uint4* dst = (uint4*)whs;
            for (int t = tid; t < 1152; t += 256) dst[t] = src[t];
        }
        __syncthreads();

        const uint2* xq = xtq + tig * 870;
        const float* xgq = xc + (size_t)(4 * tig) * 16384;

#pragma unroll
        for (int t = 0; t < 9; t++) {
            int ib = t * 256 + p0;
            uint2 A0 = bsq(xq, xgq, smeta[ib]);        // m tile 0, row gid
            uint2 A1 = bsq(xq, xgq, smeta[ib + 8]);    // m tile 0, row gid+8
            uint2 A2 = bsq(xq, xgq, smeta[ib + 16]);   // m tile 1, row gid
            uint2 A3 = bsq(xq, xgq, smeta[ib + 24]);   // m tile 1, row gid+8

            const uint4* Bp = (const uint4*)(whs + ((t * 4 + tig) * 8 + gid) * 8);
            uint4 q0 = Bp[0], q1 = Bp[1], q2 = Bp[2], q3 = Bp[3];

            mma16(acc0[0], A0.x, A1.x, A0.y, A1.y, q0.x, q0.y);
            mma16(acc1[0], A2.x, A3.x, A2.y, A3.y, q0.x, q0.y);
            mma16(acc0[1], A0.x, A1.x, A0.y, A1.y, q0.z, q0.w);
            mma16(acc1[1], A2.x, A3.x, A2.y, A3.y, q0.z, q0.w);
            mma16(acc0[2], A0.x, A1.x, A0.y, A1.y, q1.x, q1.y);
            mma16(acc1[2], A2.x, A3.x, A2.y, A3.y, q1.x, q1.y);
            mma16(acc0[3], A0.x, A1.x, A0.y, A1.y, q1.z, q1.w);
            mma16(acc1[3], A2.x, A3.x, A2.y, A3.y, q1.z, q1.w);
            mma16(acc0[4], A0.x, A1.x, A0.y, A1.y, q2.x, q2.y);
            mma16(acc1[4], A2.x, A3.x, A2.y, A3.y, q2.x, q2.y);
            mma16(acc0[5], A0.x, A1.x, A0.y, A1.y, q2.z, q2.w);
            mma16(acc1[5], A2.x, A3.x, A2.y, A3.y, q2.z, q2.w);
            mma16(acc0[6], A0.x, A1.x, A0.y, A1.y, q3.x, q3.y);
            mma16(acc1[6], A2.x, A3.x, A2.y, A3.y, q3.x, q3.y);
            mma16(acc0[7], A0.x, A1.x, A0.y, A1.y, q3.z, q3.w);
            mma16(acc1[7], A2.x, A3.x, A2.y, A3.y, q3.z, q3.w);
        }
    }

    // ---- epilogue: bias + relu ----
    int yA = ty + 2 * w, xA = tx + gid, xB = xA + 8;
    float* obp = out + (size_t)b * 64 * 16384;
#pragma unroll
    for (int nt = 0; nt < 8; nt++) {
        int o0 = nt * 8 + 2 * tig;
        float bs0 = db[o0], bs1 = db[o0 + 1];
        float* pl0 = obp + (size_t)o0 * 16384;
        float* pl1 = pl0 + 16384;
        pl0[yA * 128 + xA]       = fmaxf(acc0[nt][0] + bs0, 0.f);
        pl1[yA * 128 + xA]       = fmaxf(acc0[nt][1] + bs1, 0.f);
        pl0[yA * 128 + xB]       = fmaxf(acc0[nt][2] + bs0, 0.f);
        pl1[yA * 128 + xB]       = fmaxf(acc0[nt][3] + bs1, 0.f);
        pl0[(yA + 1) * 128 + xA] = fmaxf(acc1[nt][0] + bs0, 0.f);
        pl1[(yA + 1) * 128 + xA] = fmaxf(acc1[nt][1] + bs1, 0.f);
        pl0[(yA + 1) * 128 + xB] = fmaxf(acc1[nt][2] + bs0, 0.f);
        pl1[(yA + 1) * 128 + xB] = fmaxf(acc1[nt][3] + bs1, 0.f);
    }
}

// ===================== launch =====================
extern "C" void kernel_launch(void* const* d_in, const int* in_sizes, int n_in,
                              void* d_out, int out_size) {
    const float* x        = (const float*)d_in[0];  // (8,64,128,128)
    const float* offset_w = (const float*)d_in[1];  // (18,64,3,3)
    const float* offset_b = (const float*)d_in[2];  // (18,)
    const float* deform_w = (const float*)d_in[3];  // (64,64,3,3)
    const float* deform_b = (const float*)d_in[4];  // (64,)
    float* out = (float*)d_out;                     // (8,64,128,128)

    cudaFuncSetAttribute(deform_main_kernel,
                         cudaFuncAttributeMaxDynamicSharedMemorySize,
                         SMEM_MAIN_BYTES);

    wprep_kernel<<<36, 256>>>(deform_w, offset_w);
    offconv_kernel<<<dim3(8, 8, 8), 256>>>(x, offset_b);
    deform_main_kernel<<<dim3(8, 8, 8), 256, SMEM_MAIN_BYTES>>>(x, deform_b, out);
}